// round 12
// baseline (speedup 1.0000x reference)
#include <cuda_runtime.h>
#include <cuda_bf16.h>
#include <cstdint>

#define HWSZ 65536
#define FEAT (16*64*HWSZ)
#define PLANE ((size_t)16*HWSZ*64)

__device__ float g_featA[FEAT];
__device__ float g_featB[FEAT];
__device__ unsigned char g_wblk[147456];   // [tap 9][co 64][K 128] bf16, swizzled

#define SA_OFF 147456
#define SLOT_SZ 16896                      // 2 planes x 66px x 128B, XOR-swizzled
#define SMEM_RED (SA_OFF + 4 * SLOT_SZ)    // 215,040: 8 pairs x 2048B scratch
#define SMEM_BLK (SMEM_RED + 16384)        // 231,424 B

__device__ __forceinline__ float prelu_f(float v, float a) { return v >= 0.f ? v : a * v; }

__device__ __forceinline__ uint32_t smem_u32(const void* p) {
    uint32_t a;
    asm("{ .reg .u64 t; cvta.to.shared.u64 t, %1; cvt.u32.u64 %0, t; }" : "=r"(a) : "l"(p));
    return a;
}
__device__ __forceinline__ void ldsm4(uint32_t* r, uint32_t addr) {
    asm volatile("ldmatrix.sync.aligned.m8n8.x4.shared.b16 {%0,%1,%2,%3}, [%4];"
                 : "=r"(r[0]), "=r"(r[1]), "=r"(r[2]), "=r"(r[3]) : "r"(addr));
}
__device__ __forceinline__ void mma16816(float* d, const uint32_t* a, uint32_t b0, uint32_t b1) {
    asm volatile("mma.sync.aligned.m16n8k16.row.col.f32.bf16.bf16.f32 "
                 "{%0,%1,%2,%3},{%4,%5,%6,%7},{%8,%9},{%0,%1,%2,%3};"
                 : "+f"(d[0]), "+f"(d[1]), "+f"(d[2]), "+f"(d[3])
                 : "r"(a[0]), "r"(a[1]), "r"(a[2]), "r"(a[3]), "r"(b0), "r"(b1));
}
__device__ __forceinline__ void cpa16(uint32_t dst, const void* src, int sz) {
    asm volatile("cp.async.cg.shared.global [%0], [%1], 16, %2;" :: "r"(dst), "l"(src), "r"(sz));
}
__device__ __forceinline__ void cpa16f(uint32_t dst, const void* src) {
    asm volatile("cp.async.cg.shared.global [%0], [%1], 16;" :: "r"(dst), "l"(src));
}
#define CPA_COMMIT() asm volatile("cp.async.commit_group;")
#define CPA_WAIT1()  asm volatile("cp.async.wait_group 1;")
#define CPA_WAIT0()  asm volatile("cp.async.wait_group 0;")

// ---------------- CS sampling conv (fp32) + fused weight prep --------------
__global__ void cs_kernel(const float* __restrict__ x, const float* __restrict__ Wcs,
                          float* __restrict__ csy,
                          const float* __restrict__ Wb, unsigned char* __restrict__ wsp) {
    const int pg = blockIdx.x, n = blockIdx.y, f = threadIdx.x;
    {   // weight-prep slice: 128 blocks x 576 = 73,728 elems
        int bid = blockIdx.y * 8 + blockIdx.x;
        for (int i = bid * 576 + threadIdx.x; i < bid * 576 + 576; i += 256) {
            int k = i & 127, co = (i >> 7) & 63, tap = i >> 13;
            int ci = k & 63, seg = k >> 6;
            float w = Wb[co * 576 + ci * 9 + tap];
            __nv_bfloat16 h = __float2bfloat16(w);
            __nv_bfloat16 v = seg ? __float2bfloat16(w - __bfloat162float(h)) : h;
            int kb = 2 * k;
            int off = (kb & 128) | ((kb & 127) ^ ((co & 7) << 4));
            *(__nv_bfloat16*)(wsp + tap * 16384 + co * 256 + off) = v;
        }
    }
    __shared__ float sX[8][32];
    __shared__ float sW[256][33];
    float acc[8] = {};
    for (int k0 = 0; k0 < 1024; k0 += 32) {
        const int i = k0 >> 5;
        int p = threadIdx.x >> 5, kk = threadIdx.x & 31;
        sX[p][kk] = x[n * HWSZ + (pg * 32 + i) * 256 + p * 32 + kk];
        for (int e = threadIdx.x; e < 8192; e += 256)
            sW[e >> 5][e & 31] = Wcs[(e >> 5) * 1024 + k0 + (e & 31)];
        __syncthreads();
#pragma unroll
        for (int q = 0; q < 32; q++) {
            float w = sW[f][q];
#pragma unroll
            for (int pp = 0; pp < 8; pp++) acc[pp] += sX[pp][q] * w;
        }
        __syncthreads();
    }
#pragma unroll
    for (int pp = 0; pp < 8; pp++) csy[(n * 256 + f) * 64 + pg * 8 + pp] = acc[pp];
}

// ---------------- init reconstruction (fp32) -------------------------------
__global__ void init_kernel(const float* __restrict__ csy, const float* __restrict__ Wi,
                            float* __restrict__ initrec) {
    const int cb = blockIdx.x * 128, n = blockIdx.y;
    const int cg = threadIdx.x >> 3, pgl = threadIdx.x & 7;
    __shared__ float sX[32][64];
    __shared__ float sW[128][33];
    float acc[4][8] = {};
    for (int k0 = 0; k0 < 256; k0 += 32) {
        for (int e = threadIdx.x; e < 2048; e += 256)
            sX[e >> 6][e & 63] = csy[(n * 256 + k0 + (e >> 6)) * 64 + (e & 63)];
        for (int e = threadIdx.x; e < 4096; e += 256)
            sW[e >> 5][e & 31] = Wi[(cb + (e >> 5)) * 256 + k0 + (e & 31)];
        __syncthreads();
#pragma unroll
        for (int kk = 0; kk < 32; kk++) {
            float w0 = sW[cg*4+0][kk], w1 = sW[cg*4+1][kk], w2 = sW[cg*4+2][kk], w3 = sW[cg*4+3][kk];
#pragma unroll
            for (int pp = 0; pp < 8; pp++) {
                float xv = sX[kk][pgl * 8 + pp];
                acc[0][pp] += w0*xv; acc[1][pp] += w1*xv; acc[2][pp] += w2*xv; acc[3][pp] += w3*xv;
            }
        }
        __syncthreads();
    }
#pragma unroll
    for (int jc = 0; jc < 4; jc++) {
        int c = cb + cg * 4 + jc, jj = c >> 5, ii = c & 31;
#pragma unroll
        for (int pp = 0; pp < 8; pp++) {
            int pos = pgl * 8 + pp, by = pos >> 3, bx = pos & 7;
            initrec[n * HWSZ + (by * 32 + ii) * 256 + (bx * 32 + jj)] = acc[jc][pp];
        }
    }
}

// ------- first conv 1->64 + PReLU -> hi/lo bf16 planes ---------------------
__global__ void first_kernel(const float* __restrict__ initrec, const float* __restrict__ Wf,
                             const float* __restrict__ aM,
                             __nv_bfloat16* __restrict__ outH, __nv_bfloat16* __restrict__ outL) {
    const int tx = blockIdx.x, ty = blockIdx.y, n = blockIdx.z;
    __shared__ float sI[18][18];
    __shared__ float sWf[576];
    for (int e = threadIdx.x; e < 324; e += 256) {
        int yy = e / 18, xx = e % 18, gy = ty * 16 - 1 + yy, gx = tx * 16 - 1 + xx;
        sI[yy][xx] = ((unsigned)gy < 256u && (unsigned)gx < 256u) ? initrec[n * HWSZ + gy * 256 + gx] : 0.f;
    }
    for (int e = threadIdx.x; e < 576; e += 256) sWf[e] = Wf[e];
    __syncthreads();
    const float a = aM[0];
    const int co = threadIdx.x & 63, pl = threadIdx.x >> 6;
    float wr[9];
#pragma unroll
    for (int k = 0; k < 9; k++) wr[k] = sWf[co * 9 + k];
    for (int pxi = 0; pxi < 64; pxi++) {
        int px = pxi * 4 + pl, r = px >> 4, c = px & 15;
        float s = 0.f;
#pragma unroll
        for (int ky = 0; ky < 3; ky++)
#pragma unroll
            for (int kx = 0; kx < 3; kx++) s += wr[ky * 3 + kx] * sI[r + ky][c + kx];
        s = prelu_f(s, a);
        __nv_bfloat16 h = __float2bfloat16(s);
        __nv_bfloat16 l = __float2bfloat16(s - __bfloat162float(h));
        size_t ad = ((size_t)(n * HWSZ + (ty * 16 + r) * 256 + tx * 16 + c)) * 64 + co;
        outH[ad] = h;
        outL[ad] = l;
    }
}

// ---------- res-block conv 64->64: split-K warps (4m x 2ng(32co) x 2kg) ----
// grid (64, 16): x-col = (bx&3)*64, y-group = (bx>>2)*16. 512 thr, 16 warps.
// kg halves contract ci 0-31 / 32-63; partials summed via smem scratch.
__device__ __forceinline__ void load_row(uint32_t sb, const __nv_bfloat16* inH,
                                         const __nv_bfloat16* inL, int n, int y,
                                         int x0, int slot, int tid) {
    uint32_t base = sb + SA_OFF + (uint32_t)slot * SLOT_SZ;
    for (int idx = tid; idx < 1056; idx += 512) {
        int plane = idx >= 528;
        int i2 = plane ? idx - 528 : idx;
        int px = i2 >> 3, ch = i2 & 7;
        int gx = x0 - 1 + px;
        bool ok = (unsigned)y < 256u && (unsigned)gx < 256u;
        const __nv_bfloat16* bp = plane ? inL : inH;
        const __nv_bfloat16* sp = ok ? bp + ((size_t)(n * HWSZ + y * 256 + gx)) * 64 + ch * 8 : bp;
        uint32_t dst = base + (uint32_t)plane * 8448 + (uint32_t)px * 128 +
                       (((uint32_t)ch << 4) ^ (((uint32_t)px & 7) << 4));
        cpa16(dst, sp, ok ? 16 : 0);
    }
}

template <bool RES>
__global__ void __launch_bounds__(512, 1) blk_mma(
    const __nv_bfloat16* __restrict__ inH, const __nv_bfloat16* __restrict__ inL,
    const unsigned char* __restrict__ wblk, const float* __restrict__ aB,
    __nv_bfloat16* __restrict__ outH, __nv_bfloat16* __restrict__ outL) {
    extern __shared__ unsigned char sm[];
    const uint32_t sb = smem_u32(sm);
    const int tid = threadIdx.x, w = tid >> 5, lane = tid & 31;
    const int n = blockIdx.y, x0 = (blockIdx.x & 3) * 64, y0 = (blockIdx.x >> 2) * 16;
    const int m = w & 3, ng = (w >> 2) & 1, kg = w >> 3;

    // Prologue: B (all taps) + rows rel 0,1,2 (group A); rel 3 (group B).
    {
        const uint4* s = (const uint4*)wblk;
        for (int i = tid; i < 9216; i += 512) cpa16f(sb + i * 16, s + i);
    }
    load_row(sb, inH, inL, n, y0 - 1, x0, 0, tid);
    load_row(sb, inH, inL, n, y0,     x0, 1, tid);
    load_row(sb, inH, inL, n, y0 + 1, x0, 2, tid);
    CPA_COMMIT();
    load_row(sb, inH, inL, n, y0 + 2, x0, 3, tid);
    CPA_COMMIT();

    // per-lane constants
    const int pxl = m * 16 + (lane & 15);
    const uint32_t h16 = ((lane >> 4) & 1) << 4;
    const int co_l = (lane & 7) + ((lane >> 4) & 1) * 8;
    const int kb_l = ((lane >> 3) & 1) * 16;
    const int sx = (lane & 7) << 4;
    uint32_t offk[8];
#pragma unroll
    for (int j = 0; j < 8; j++) {
        int kb = j * 32 + kb_l;
        offk[j] = (uint32_t)((kb & 128) | ((kb & 127) ^ sx));
    }
    const uint32_t bb0 = sb + (uint32_t)(ng * 32 + co_l) * 256;
    const uint32_t bb1 = bb0 + 4096;   // +16 co
    float4* redp = (float4*)(sm + SMEM_RED + (m * 2 + ng) * 2048);
    const float a = aB[0];

    for (int t = 0; t < 8; t++) {
        uint32_t slotA[4];
#pragma unroll
        for (int j = 0; j < 4; j++)
            slotA[j] = sb + SA_OFF + (uint32_t)((2 * t + j) & 3) * SLOT_SZ;

        float acc[2][4][4];
#pragma unroll
        for (int r = 0; r < 2; r++)
#pragma unroll
            for (int g = 0; g < 4; g++)
#pragma unroll
                for (int j = 0; j < 4; j++) acc[r][g][j] = 0.f;

        CPA_WAIT1();          // rels <= 2t+2 resident; rel 2t+3 in flight
        __syncthreads();

#pragma unroll
        for (int ky = 0; ky < 3; ky++) {
            if (ky == 2) {    // rel 2t+3 first needed at r=1,ky=2
                CPA_WAIT0();
                __syncthreads();
            }
#pragma unroll
            for (int kx = 0; kx < 3; kx++) {
                const uint32_t px = (uint32_t)(pxl + kx);
                const uint32_t sw = (px & 7) << 4;
                const uint32_t a0 = slotA[ky + 0] + px * 128;
                const uint32_t a1 = slotA[ky + 1] + px * 128;
                const int tap = ky * 3 + kx;
                const uint32_t bt0 = bb0 + (uint32_t)tap * 16384;
                const uint32_t bt1 = bb1 + (uint32_t)tap * 16384;
#pragma unroll
                for (int qi = 0; qi < 2; qi++) {
                    const int q = kg * 2 + qi;
                    const uint32_t off = (h16 | ((uint32_t)q << 5)) ^ sw;
                    uint32_t ah0[4], ah1[4], al0[4], al1[4];
                    uint32_t bh0[4], bh1[4], bl0[4], bl1[4];
                    ldsm4(ah0, a0 + off);
                    ldsm4(ah1, a1 + off);
                    ldsm4(al0, a0 + 8448 + off);
                    ldsm4(al1, a1 + 8448 + off);
                    ldsm4(bh0, bt0 + offk[q]);
                    ldsm4(bh1, bt1 + offk[q]);
                    ldsm4(bl0, bt0 + offk[4 + q]);
                    ldsm4(bl1, bt1 + offk[4 + q]);
                    // wh x (xh, xl)
                    mma16816(acc[0][0], ah0, bh0[0], bh0[1]);
                    mma16816(acc[0][1], ah0, bh0[2], bh0[3]);
                    mma16816(acc[0][2], ah0, bh1[0], bh1[1]);
                    mma16816(acc[0][3], ah0, bh1[2], bh1[3]);
                    mma16816(acc[1][0], ah1, bh0[0], bh0[1]);
                    mma16816(acc[1][1], ah1, bh0[2], bh0[3]);
                    mma16816(acc[1][2], ah1, bh1[0], bh1[1]);
                    mma16816(acc[1][3], ah1, bh1[2], bh1[3]);
                    mma16816(acc[0][0], al0, bh0[0], bh0[1]);
                    mma16816(acc[0][1], al0, bh0[2], bh0[3]);
                    mma16816(acc[0][2], al0, bh1[0], bh1[1]);
                    mma16816(acc[0][3], al0, bh1[2], bh1[3]);
                    mma16816(acc[1][0], al1, bh0[0], bh0[1]);
                    mma16816(acc[1][1], al1, bh0[2], bh0[3]);
                    mma16816(acc[1][2], al1, bh1[0], bh1[1]);
                    mma16816(acc[1][3], al1, bh1[2], bh1[3]);
                    // wl x xh
                    mma16816(acc[0][0], ah0, bl0[0], bl0[1]);
                    mma16816(acc[0][1], ah0, bl0[2], bl0[3]);
                    mma16816(acc[0][2], ah0, bl1[0], bl1[1]);
                    mma16816(acc[0][3], ah0, bl1[2], bl1[3]);
                    mma16816(acc[1][0], ah1, bl0[0], bl0[1]);
                    mma16816(acc[1][1], ah1, bl0[2], bl0[3]);
                    mma16816(acc[1][2], ah1, bl1[0], bl1[1]);
                    mma16816(acc[1][3], ah1, bl1[2], bl1[3]);
                }
            }
        }
        __syncthreads();      // slab reads done

        // issue next tile's rows — overlap with reduction/epilogue
        if (t < 7) {
            load_row(sb, inH, inL, n, y0 + 2 * t + 3, x0, (2 * t + 4) & 3, tid);
            CPA_COMMIT();
            load_row(sb, inH, inL, n, y0 + 2 * t + 4, x0, (2 * t + 5) & 3, tid);
            CPA_COMMIT();
        }

        // cross-kg reduction + epilogue, one row-phase at a time
        const int r0 = lane >> 2;
#pragma unroll
        for (int r = 0; r < 2; r++) {
            if (kg == 1) {
#pragma unroll
                for (int g = 0; g < 4; g++)
                    redp[g * 32 + lane] = make_float4(acc[r][g][0], acc[r][g][1],
                                                      acc[r][g][2], acc[r][g][3]);
            }
            __syncthreads();
            if (kg == 0) {
#pragma unroll
                for (int g = 0; g < 4; g++) {
                    float4 o = redp[g * 32 + lane];
                    acc[r][g][0] += o.x; acc[r][g][1] += o.y;
                    acc[r][g][2] += o.z; acc[r][g][3] += o.w;
                }
                const size_t rowbase = (size_t)(n * HWSZ + (y0 + 2 * t + r) * 256 + x0 + m * 16);
#pragma unroll
                for (int h = 0; h < 2; h++) {
                    size_t pa = (rowbase + r0 + h * 8) * 64 + ng * 32 + (lane & 3) * 2;
#pragma unroll
                    for (int g = 0; g < 4; g++) {
                        size_t ad = pa + g * 8;
                        float v0 = acc[r][g][h * 2 + 0], v1 = acc[r][g][h * 2 + 1];
                        if (RES) {
                            uint32_t h2 = *(const uint32_t*)(outH + ad);
                            uint32_t l2 = *(const uint32_t*)(outL + ad);
                            v0 += __bfloat162float(__ushort_as_bfloat16((unsigned short)(h2 & 0xffff))) +
                                  __bfloat162float(__ushort_as_bfloat16((unsigned short)(l2 & 0xffff)));
                            v1 += __bfloat162float(__ushort_as_bfloat16((unsigned short)(h2 >> 16))) +
                                  __bfloat162float(__ushort_as_bfloat16((unsigned short)(l2 >> 16)));
                        }
                        v0 = prelu_f(v0, a);
                        v1 = prelu_f(v1, a);
                        __nv_bfloat16 h0 = __float2bfloat16(v0), h1 = __float2bfloat16(v1);
                        __nv_bfloat16 l0 = __float2bfloat16(v0 - __bfloat162float(h0));
                        __nv_bfloat16 l1 = __float2bfloat16(v1 - __bfloat162float(h1));
                        *(uint32_t*)(outH + ad) = (uint32_t)__bfloat16_as_ushort(h0) |
                                                  ((uint32_t)__bfloat16_as_ushort(h1) << 16);
                        *(uint32_t*)(outL + ad) = (uint32_t)__bfloat16_as_ushort(l0) |
                                                  ((uint32_t)__bfloat16_as_ushort(l1) << 16);
                    }
                }
            }
            __syncthreads();  // scratch free / slot reuse safe
        }
    }
}

// --------- last conv: (feat planes + initrec) -> 1 channel -----------------
__global__ void last_kernel(const __nv_bfloat16* __restrict__ featH,
                            const __nv_bfloat16* __restrict__ featL,
                            const float* __restrict__ initrec,
                            const float* __restrict__ Wl, float* __restrict__ out) {
    const int tx = blockIdx.x, ty = blockIdx.y, n = blockIdx.z;
    __shared__ float sInit[18][18];
    __shared__ float sIn[8][18][20];
    __shared__ float sWl[576];
    for (int e = threadIdx.x; e < 324; e += 256) {
        int yy = e / 18, xx = e % 18, gy = ty * 16 - 1 + yy, gx = tx * 16 - 1 + xx;
        sInit[yy][xx] = ((unsigned)gy < 256u && (unsigned)gx < 256u) ? initrec[n * HWSZ + gy * 256 + gx] : 0.f;
    }
    for (int e = threadIdx.x; e < 576; e += 256) sWl[e] = Wl[e];
    __syncthreads();
    const int r = threadIdx.x >> 4, c = threadIdx.x & 15;
    float acc = 0.f;
    for (int ci0 = 0; ci0 < 64; ci0 += 8) {
        for (int e = threadIdx.x; e < 324; e += 256) {
            int yy = e / 18, xx = e % 18;
            int gy = ty * 16 - 1 + yy, gx = tx * 16 - 1 + xx;
            float init = sInit[yy][xx];
            if ((unsigned)gy < 256u && (unsigned)gx < 256u) {
                size_t ad = (size_t)(n * HWSZ + gy * 256 + gx) * 64 + ci0;
                uint4 h4 = *(const uint4*)(featH + ad);
                uint4 l4 = *(const uint4*)(featL + ad);
                const uint32_t* hp = &h4.x;
                const uint32_t* lp = &l4.x;
#pragma unroll
                for (int p = 0; p < 4; p++) {
                    float v0 = __bfloat162float(__ushort_as_bfloat16((unsigned short)(hp[p] & 0xffff))) +
                               __bfloat162float(__ushort_as_bfloat16((unsigned short)(lp[p] & 0xffff)));
                    float v1 = __bfloat162float(__ushort_as_bfloat16((unsigned short)(hp[p] >> 16))) +
                               __bfloat162float(__ushort_as_bfloat16((unsigned short)(lp[p] >> 16)));
                    sIn[2 * p + 0][yy][xx] = v0 + init;
                    sIn[2 * p + 1][yy][xx] = v1 + init;
                }
            } else {
#pragma unroll
                for (int j = 0; j < 8; j++) sIn[j][yy][xx] = init;
            }
        }
        __syncthreads();
#pragma unroll 1
        for (int ci = 0; ci < 8; ci++)
#pragma unroll
            for (int ky = 0; ky < 3; ky++)
#pragma unroll
                for (int kx = 0; kx < 3; kx++)
                    acc += sIn[ci][r + ky][c + kx] * sWl[(ci0 + ci) * 9 + ky * 3 + kx];
        __syncthreads();
    }
    out[n * HWSZ + (ty * 16 + r) * 256 + (tx * 16 + c)] = acc;
}

// ---------------------------------------------------------------------------
extern "C" void kernel_launch(void* const* d_in, const int* in_sizes, int n_in,
                              void* d_out, int out_size) {
    (void)in_sizes; (void)n_in; (void)out_size;
    const float* x   = (const float*)d_in[0];
    const float* Wcs = (const float*)d_in[1];
    const float* Wi  = (const float*)d_in[2];
    const float* Wf  = (const float*)d_in[3];
    const float* Wb  = (const float*)d_in[4];
    const float* Wl  = (const float*)d_in[5];
    const float* aM  = (const float*)d_in[6];
    const float* aB  = (const float*)d_in[7];

    float* out     = (float*)d_out;
    float* csy     = out + 16 * HWSZ;
    float* initrec = csy + 16 * 256 * 64;

    void *pA = nullptr, *pB = nullptr, *pW = nullptr;
    cudaGetSymbolAddress(&pA, g_featA);
    cudaGetSymbolAddress(&pB, g_featB);
    cudaGetSymbolAddress(&pW, g_wblk);
    __nv_bfloat16* hiA = (__nv_bfloat16*)pA;
    __nv_bfloat16* loA = hiA + PLANE;
    __nv_bfloat16* hiB = (__nv_bfloat16*)pB;
    __nv_bfloat16* loB = hiB + PLANE;
    unsigned char* wblk = (unsigned char*)pW;

    cudaFuncSetAttribute(blk_mma<false>, cudaFuncAttributeMaxDynamicSharedMemorySize, SMEM_BLK);
    cudaFuncSetAttribute(blk_mma<true>,  cudaFuncAttributeMaxDynamicSharedMemorySize, SMEM_BLK);

    cs_kernel<<<dim3(8, 16), 256>>>(x, Wcs, csy, Wb, wblk);
    init_kernel<<<dim3(8, 16), 256>>>(csy, Wi, initrec);
    first_kernel<<<dim3(16, 16, 16), 256>>>(initrec, Wf, aM, hiA, loA);

    for (int i = 0; i < 4; i++) {
        blk_mma<false><<<dim3(64, 16), 512, SMEM_BLK>>>(hiA, loA, wblk, aB, hiB, loB);
        blk_mma<true><<<dim3(64, 16), 512, SMEM_BLK>>>(hiB, loB, wblk, aB, hiA, loA);
    }
    last_kernel<<<dim3(16, 16, 16), 256>>>(hiA, loA, initrec, Wl, out);
}

// round 13
// speedup vs baseline: 1.1515x; 1.1515x over previous
#include <cuda_runtime.h>
#include <cuda_bf16.h>
#include <cstdint>

#define HWSZ 65536
#define FEAT (16*64*HWSZ)
#define PLANE ((size_t)16*HWSZ*64)

__device__ float g_featA[FEAT];
__device__ float g_featB[FEAT];
__device__ unsigned char g_wblk[147456];   // [tap 9][co 64][K 128] bf16, swizzled

#define SA_OFF 147456
#define SLOT_SZ 16896                      // 2 planes x 66px x 128B, XOR-swizzled
#define SMEM_BLK (147456 + 5 * SLOT_SZ)    // 231,936 B

__device__ __forceinline__ float prelu_f(float v, float a) { return v >= 0.f ? v : a * v; }

__device__ __forceinline__ uint32_t smem_u32(const void* p) {
    uint32_t a;
    asm("{ .reg .u64 t; cvta.to.shared.u64 t, %1; cvt.u32.u64 %0, t; }" : "=r"(a) : "l"(p));
    return a;
}
__device__ __forceinline__ void ldsm4(uint32_t* r, uint32_t addr) {
    asm volatile("ldmatrix.sync.aligned.m8n8.x4.shared.b16 {%0,%1,%2,%3}, [%4];"
                 : "=r"(r[0]), "=r"(r[1]), "=r"(r[2]), "=r"(r[3]) : "r"(addr));
}
__device__ __forceinline__ void mma16816(float* d, const uint32_t* a, uint32_t b0, uint32_t b1) {
    asm volatile("mma.sync.aligned.m16n8k16.row.col.f32.bf16.bf16.f32 "
                 "{%0,%1,%2,%3},{%4,%5,%6,%7},{%8,%9},{%0,%1,%2,%3};"
                 : "+f"(d[0]), "+f"(d[1]), "+f"(d[2]), "+f"(d[3])
                 : "r"(a[0]), "r"(a[1]), "r"(a[2]), "r"(a[3]), "r"(b0), "r"(b1));
}
__device__ __forceinline__ void cpa16(uint32_t dst, const void* src, int sz) {
    asm volatile("cp.async.cg.shared.global [%0], [%1], 16, %2;" :: "r"(dst), "l"(src), "r"(sz));
}
__device__ __forceinline__ void cpa16f(uint32_t dst, const void* src) {
    asm volatile("cp.async.cg.shared.global [%0], [%1], 16;" :: "r"(dst), "l"(src));
}
#define CPA_COMMIT() asm volatile("cp.async.commit_group;")
#define CPA_WAIT0()  asm volatile("cp.async.wait_group 0;")

// ---------------- CS sampling conv (fp32) + fused weight prep --------------
__global__ void cs_kernel(const float* __restrict__ x, const float* __restrict__ Wcs,
                          float* __restrict__ csy,
                          const float* __restrict__ Wb, unsigned char* __restrict__ wsp) {
    const int pg = blockIdx.x, n = blockIdx.y, f = threadIdx.x;
    {   // weight-prep slice: 128 blocks x 576 = 73,728 elems
        int bid = blockIdx.y * 8 + blockIdx.x;
        for (int i = bid * 576 + threadIdx.x; i < bid * 576 + 576; i += 256) {
            int k = i & 127, co = (i >> 7) & 63, tap = i >> 13;
            int ci = k & 63, seg = k >> 6;
            float w = Wb[co * 576 + ci * 9 + tap];
            __nv_bfloat16 h = __float2bfloat16(w);
            __nv_bfloat16 v = seg ? __float2bfloat16(w - __bfloat162float(h)) : h;
            int kb = 2 * k;
            int off = (kb & 128) | ((kb & 127) ^ ((co & 7) << 4));
            *(__nv_bfloat16*)(wsp + tap * 16384 + co * 256 + off) = v;
        }
    }
    __shared__ float sX[8][32];
    __shared__ float sW[256][33];
    float acc[8] = {};
    for (int k0 = 0; k0 < 1024; k0 += 32) {
        const int i = k0 >> 5;
        int p = threadIdx.x >> 5, kk = threadIdx.x & 31;
        sX[p][kk] = x[n * HWSZ + (pg * 32 + i) * 256 + p * 32 + kk];
        for (int e = threadIdx.x; e < 8192; e += 256)
            sW[e >> 5][e & 31] = Wcs[(e >> 5) * 1024 + k0 + (e & 31)];
        __syncthreads();
#pragma unroll
        for (int q = 0; q < 32; q++) {
            float w = sW[f][q];
#pragma unroll
            for (int pp = 0; pp < 8; pp++) acc[pp] += sX[pp][q] * w;
        }
        __syncthreads();
    }
#pragma unroll
    for (int pp = 0; pp < 8; pp++) csy[(n * 256 + f) * 64 + pg * 8 + pp] = acc[pp];
}

// ---------------- init reconstruction (fp32) -------------------------------
__global__ void init_kernel(const float* __restrict__ csy, const float* __restrict__ Wi,
                            float* __restrict__ initrec) {
    const int cb = blockIdx.x * 128, n = blockIdx.y;
    const int cg = threadIdx.x >> 3, pgl = threadIdx.x & 7;
    __shared__ float sX[32][64];
    __shared__ float sW[128][33];
    float acc[4][8] = {};
    for (int k0 = 0; k0 < 256; k0 += 32) {
        for (int e = threadIdx.x; e < 2048; e += 256)
            sX[e >> 6][e & 63] = csy[(n * 256 + k0 + (e >> 6)) * 64 + (e & 63)];
        for (int e = threadIdx.x; e < 4096; e += 256)
            sW[e >> 5][e & 31] = Wi[(cb + (e >> 5)) * 256 + k0 + (e & 31)];
        __syncthreads();
#pragma unroll
        for (int kk = 0; kk < 32; kk++) {
            float w0 = sW[cg*4+0][kk], w1 = sW[cg*4+1][kk], w2 = sW[cg*4+2][kk], w3 = sW[cg*4+3][kk];
#pragma unroll
            for (int pp = 0; pp < 8; pp++) {
                float xv = sX[kk][pgl * 8 + pp];
                acc[0][pp] += w0*xv; acc[1][pp] += w1*xv; acc[2][pp] += w2*xv; acc[3][pp] += w3*xv;
            }
        }
        __syncthreads();
    }
#pragma unroll
    for (int jc = 0; jc < 4; jc++) {
        int c = cb + cg * 4 + jc, jj = c >> 5, ii = c & 31;
#pragma unroll
        for (int pp = 0; pp < 8; pp++) {
            int pos = pgl * 8 + pp, by = pos >> 3, bx = pos & 7;
            initrec[n * HWSZ + (by * 32 + ii) * 256 + (bx * 32 + jj)] = acc[jc][pp];
        }
    }
}

// ------- first conv 1->64 + PReLU -> hi/lo bf16 planes ---------------------
__global__ void first_kernel(const float* __restrict__ initrec, const float* __restrict__ Wf,
                             const float* __restrict__ aM,
                             __nv_bfloat16* __restrict__ outH, __nv_bfloat16* __restrict__ outL) {
    const int tx = blockIdx.x, ty = blockIdx.y, n = blockIdx.z;
    __shared__ float sI[18][18];
    __shared__ float sWf[576];
    for (int e = threadIdx.x; e < 324; e += 256) {
        int yy = e / 18, xx = e % 18, gy = ty * 16 - 1 + yy, gx = tx * 16 - 1 + xx;
        sI[yy][xx] = ((unsigned)gy < 256u && (unsigned)gx < 256u) ? initrec[n * HWSZ + gy * 256 + gx] : 0.f;
    }
    for (int e = threadIdx.x; e < 576; e += 256) sWf[e] = Wf[e];
    __syncthreads();
    const float a = aM[0];
    const int co = threadIdx.x & 63, pl = threadIdx.x >> 6;
    float wr[9];
#pragma unroll
    for (int k = 0; k < 9; k++) wr[k] = sWf[co * 9 + k];
    for (int pxi = 0; pxi < 64; pxi++) {
        int px = pxi * 4 + pl, r = px >> 4, c = px & 15;
        float s = 0.f;
#pragma unroll
        for (int ky = 0; ky < 3; ky++)
#pragma unroll
            for (int kx = 0; kx < 3; kx++) s += wr[ky * 3 + kx] * sI[r + ky][c + kx];
        s = prelu_f(s, a);
        __nv_bfloat16 h = __float2bfloat16(s);
        __nv_bfloat16 l = __float2bfloat16(s - __bfloat162float(h));
        size_t ad = ((size_t)(n * HWSZ + (ty * 16 + r) * 256 + tx * 16 + c)) * 64 + co;
        outH[ad] = h;
        outL[ad] = l;
    }
}

// ---------- res-block conv 64->64: 2-row tiles, 16 warps, 5-slot ring ------
// grid (64, 16): x-col = (bx&3)*64, y-group = (bx>>2)*16. 512 thr, 16 warps:
// warp = m(4, 16px) x ng(4, 16co). 2 syncs/tile, no mid-compute barrier.
__device__ __forceinline__ void load_row(uint32_t sb, const __nv_bfloat16* inH,
                                         const __nv_bfloat16* inL, int n, int y,
                                         int x0, int slot, int tid) {
    uint32_t base = sb + SA_OFF + (uint32_t)slot * SLOT_SZ;
    for (int idx = tid; idx < 1056; idx += 512) {
        int plane = idx >= 528;
        int i2 = plane ? idx - 528 : idx;
        int px = i2 >> 3, ch = i2 & 7;
        int gx = x0 - 1 + px;
        bool ok = (unsigned)y < 256u && (unsigned)gx < 256u;
        const __nv_bfloat16* bp = plane ? inL : inH;
        const __nv_bfloat16* sp = ok ? bp + ((size_t)(n * HWSZ + y * 256 + gx)) * 64 + ch * 8 : bp;
        uint32_t dst = base + (uint32_t)plane * 8448 + (uint32_t)px * 128 +
                       (((uint32_t)ch << 4) ^ (((uint32_t)px & 7) << 4));
        cpa16(dst, sp, ok ? 16 : 0);
    }
}

template <bool RES>
__global__ void __launch_bounds__(512, 1) blk_mma(
    const __nv_bfloat16* __restrict__ inH, const __nv_bfloat16* __restrict__ inL,
    const unsigned char* __restrict__ wblk, const float* __restrict__ aB,
    __nv_bfloat16* __restrict__ outH, __nv_bfloat16* __restrict__ outL) {
    extern __shared__ unsigned char sm[];
    const uint32_t sb = smem_u32(sm);
    const int tid = threadIdx.x, w = tid >> 5, lane = tid & 31;
    const int n = blockIdx.y, x0 = (blockIdx.x & 3) * 64, y0 = (blockIdx.x >> 2) * 16;
    const int m = w & 3, ng = w >> 2;

    // Prologue: B (all taps) + rows rel 0..3 (slots 0..3), one group.
    {
        const uint4* s = (const uint4*)wblk;
        for (int i = tid; i < 9216; i += 512) cpa16f(sb + i * 16, s + i);
    }
    load_row(sb, inH, inL, n, y0 - 1, x0, 0, tid);
    load_row(sb, inH, inL, n, y0,     x0, 1, tid);
    load_row(sb, inH, inL, n, y0 + 1, x0, 2, tid);
    load_row(sb, inH, inL, n, y0 + 2, x0, 3, tid);
    CPA_COMMIT();

    // per-lane constants
    const int pxl = m * 16 + (lane & 15);
    const uint32_t h16 = ((lane >> 4) & 1) << 4;
    const int co_l = (lane & 7) + ((lane >> 4) & 1) * 8;
    const int kb_l = ((lane >> 3) & 1) * 16;
    const int sx = (lane & 7) << 4;
    uint32_t offk[8];
#pragma unroll
    for (int j = 0; j < 8; j++) {
        int kb = j * 32 + kb_l;
        offk[j] = (uint32_t)((kb & 128) | ((kb & 127) ^ sx));
    }
    const uint32_t bbase = sb + (uint32_t)(ng * 16 + co_l) * 256;
    const float a = aB[0];

    for (int t = 0; t < 8; t++) {
        // all rows for this tile (rels 2t..2t+3) resident after this wait
        CPA_WAIT0();
        __syncthreads();

        // prefetch first next-tile row: rel 2t+4 -> slot (2t+4)%5 = (2t-1)%5 (dead)
        if (t < 7) {
            load_row(sb, inH, inL, n, y0 + 2 * t + 3, x0, (2 * t + 4) % 5, tid);
            CPA_COMMIT();
        }

        uint32_t slotA[4];
#pragma unroll
        for (int j = 0; j < 4; j++)
            slotA[j] = sb + SA_OFF + (uint32_t)((2 * t + j) % 5) * SLOT_SZ;

        float acc[2][2][4];
#pragma unroll
        for (int r = 0; r < 2; r++)
#pragma unroll
            for (int i = 0; i < 2; i++)
#pragma unroll
                for (int j = 0; j < 4; j++) acc[r][i][j] = 0.f;

#pragma unroll
        for (int ky = 0; ky < 3; ky++) {
#pragma unroll
            for (int kx = 0; kx < 3; kx++) {
                const uint32_t px = (uint32_t)(pxl + kx);
                const uint32_t sw = (px & 7) << 4;
                const uint32_t a0 = slotA[ky + 0] + px * 128;
                const uint32_t a1 = slotA[ky + 1] + px * 128;
                const uint32_t bt = bbase + (uint32_t)(ky * 3 + kx) * 16384;
#pragma unroll
                for (int q = 0; q < 4; q++) {
                    const uint32_t off = (h16 | ((uint32_t)q << 5)) ^ sw;
                    uint32_t ah0[4], ah1[4], al0[4], al1[4], bh[4], bl[4];
                    ldsm4(ah0, a0 + off);
                    ldsm4(ah1, a1 + off);
                    ldsm4(al0, a0 + 8448 + off);
                    ldsm4(al1, a1 + 8448 + off);
                    ldsm4(bh, bt + offk[q]);
                    ldsm4(bl, bt + offk[4 + q]);
                    mma16816(acc[0][0], ah0, bh[0], bh[1]);
                    mma16816(acc[0][1], ah0, bh[2], bh[3]);
                    mma16816(acc[1][0], ah1, bh[0], bh[1]);
                    mma16816(acc[1][1], ah1, bh[2], bh[3]);
                    mma16816(acc[0][0], al0, bh[0], bh[1]);
                    mma16816(acc[0][1], al0, bh[2], bh[3]);
                    mma16816(acc[1][0], al1, bh[0], bh[1]);
                    mma16816(acc[1][1], al1, bh[2], bh[3]);
                    mma16816(acc[0][0], ah0, bl[0], bl[1]);
                    mma16816(acc[0][1], ah0, bl[2], bl[3]);
                    mma16816(acc[1][0], ah1, bl[0], bl[1]);
                    mma16816(acc[1][1], ah1, bl[2], bl[3]);
                }
            }
        }
        __syncthreads();      // slab reads done (frees slot (2t)%5)

        // second next-tile row: rel 2t+5 -> slot (2t+5)%5 = (2t)%5 (just freed)
        if (t < 7) {
            load_row(sb, inH, inL, n, y0 + 2 * t + 4, x0, (2 * t + 5) % 5, tid);
            CPA_COMMIT();
        }

        // epilogue: residual + PReLU + split store (2 rows x 16px x 16co)
        const int r0 = lane >> 2;
#pragma unroll
        for (int r = 0; r < 2; r++) {
            const size_t rowbase = (size_t)(n * HWSZ + (y0 + 2 * t + r) * 256 + x0 + m * 16);
#pragma unroll
            for (int h = 0; h < 2; h++) {
                size_t pa = (rowbase + r0 + h * 8) * 64 + ng * 16 + (lane & 3) * 2;
#pragma unroll
                for (int q = 0; q < 2; q++) {
                    size_t ad = pa + q * 8;
                    float v0 = acc[r][q][h * 2 + 0], v1 = acc[r][q][h * 2 + 1];
                    if (RES) {
                        uint32_t h2 = *(const uint32_t*)(outH + ad);
                        uint32_t l2 = *(const uint32_t*)(outL + ad);
                        v0 += __bfloat162float(__ushort_as_bfloat16((unsigned short)(h2 & 0xffff))) +
                              __bfloat162float(__ushort_as_bfloat16((unsigned short)(l2 & 0xffff)));
                        v1 += __bfloat162float(__ushort_as_bfloat16((unsigned short)(h2 >> 16))) +
                              __bfloat162float(__ushort_as_bfloat16((unsigned short)(l2 >> 16)));
                    }
                    v0 = prelu_f(v0, a);
                    v1 = prelu_f(v1, a);
                    __nv_bfloat16 h0 = __float2bfloat16(v0), h1 = __float2bfloat16(v1);
                    __nv_bfloat16 l0 = __float2bfloat16(v0 - __bfloat162float(h0));
                    __nv_bfloat16 l1 = __float2bfloat16(v1 - __bfloat162float(h1));
                    *(uint32_t*)(outH + ad) = (uint32_t)__bfloat16_as_ushort(h0) |
                                              ((uint32_t)__bfloat16_as_ushort(h1) << 16);
                    *(uint32_t*)(outL + ad) = (uint32_t)__bfloat16_as_ushort(l0) |
                                              ((uint32_t)__bfloat16_as_ushort(l1) << 16);
                }
            }
        }
        // no trailing sync: next tile begins with CPA_WAIT0 + __syncthreads
    }
}

// --------- last conv: (feat planes + initrec) -> 1 channel -----------------
__global__ void last_kernel(const __nv_bfloat16* __restrict__ featH,
                            const __nv_bfloat16* __restrict__ featL,
                            const float* __restrict__ initrec,
                            const float* __restrict__ Wl, float* __restrict__ out) {
    const int tx = blockIdx.x, ty = blockIdx.y, n = blockIdx.z;
    __shared__ float sInit[18][18];
    __shared__ float sIn[8][18][20];
    __shared__ float sWl[576];
    for (int e = threadIdx.x; e < 324; e += 256) {
        int yy = e / 18, xx = e % 18, gy = ty * 16 - 1 + yy, gx = tx * 16 - 1 + xx;
        sInit[yy][xx] = ((unsigned)gy < 256u && (unsigned)gx < 256u) ? initrec[n * HWSZ + gy * 256 + gx] : 0.f;
    }
    for (int e = threadIdx.x; e < 576; e += 256) sWl[e] = Wl[e];
    __syncthreads();
    const int r = threadIdx.x >> 4, c = threadIdx.x & 15;
    float acc = 0.f;
    for (int ci0 = 0; ci0 < 64; ci0 += 8) {
        for (int e = threadIdx.x; e < 324; e += 256) {
            int yy = e / 18, xx = e % 18;
            int gy = ty * 16 - 1 + yy, gx = tx * 16 - 1 + xx;
            float init = sInit[yy][xx];
            if ((unsigned)gy < 256u && (unsigned)gx < 256u) {
                size_t ad = (size_t)(n * HWSZ + gy * 256 + gx) * 64 + ci0;
                uint4 h4 = *(const uint4*)(featH + ad);
                uint4 l4 = *(const uint4*)(featL + ad);
                const uint32_t* hp = &h4.x;
                const uint32_t* lp = &l4.x;
#pragma unroll
                for (int p = 0; p < 4; p++) {
                    float v0 = __bfloat162float(__ushort_as_bfloat16((unsigned short)(hp[p] & 0xffff))) +
                               __bfloat162float(__ushort_as_bfloat16((unsigned short)(lp[p] & 0xffff)));
                    float v1 = __bfloat162float(__ushort_as_bfloat16((unsigned short)(hp[p] >> 16))) +
                               __bfloat162float(__ushort_as_bfloat16((unsigned short)(lp[p] >> 16)));
                    sIn[2 * p + 0][yy][xx] = v0 + init;
                    sIn[2 * p + 1][yy][xx] = v1 + init;
                }
            } else {
#pragma unroll
                for (int j = 0; j < 8; j++) sIn[j][yy][xx] = init;
            }
        }
        __syncthreads();
#pragma unroll 1
        for (int ci = 0; ci < 8; ci++)
#pragma unroll
            for (int ky = 0; ky < 3; ky++)
#pragma unroll
                for (int kx = 0; kx < 3; kx++)
                    acc += sIn[ci][r + ky][c + kx] * sWl[(ci0 + ci) * 9 + ky * 3 + kx];
        __syncthreads();
    }
    out[n * HWSZ + (ty * 16 + r) * 256 + (tx * 16 + c)] = acc;
}

// ---------------------------------------------------------------------------
extern "C" void kernel_launch(void* const* d_in, const int* in_sizes, int n_in,
                              void* d_out, int out_size) {
    (void)in_sizes; (void)n_in; (void)out_size;
    const float* x   = (const float*)d_in[0];
    const float* Wcs = (const float*)d_in[1];
    const float* Wi  = (const float*)d_in[2];
    const float* Wf  = (const float*)d_in[3];
    const float* Wb  = (const float*)d_in[4];
    const float* Wl  = (const float*)d_in[5];
    const float* aM  = (const float*)d_in[6];
    const float* aB  = (const float*)d_in[7];

    float* out     = (float*)d_out;
    float* csy     = out + 16 * HWSZ;
    float* initrec = csy + 16 * 256 * 64;

    void *pA = nullptr, *pB = nullptr, *pW = nullptr;
    cudaGetSymbolAddress(&pA, g_featA);
    cudaGetSymbolAddress(&pB, g_featB);
    cudaGetSymbolAddress(&pW, g_wblk);
    __nv_bfloat16* hiA = (__nv_bfloat16*)pA;
    __nv_bfloat16* loA = hiA + PLANE;
    __nv_bfloat16* hiB = (__nv_bfloat16*)pB;
    __nv_bfloat16* loB = hiB + PLANE;
    unsigned char* wblk = (unsigned char*)pW;

    cudaFuncSetAttribute(blk_mma<false>, cudaFuncAttributeMaxDynamicSharedMemorySize, SMEM_BLK);
    cudaFuncSetAttribute(blk_mma<true>,  cudaFuncAttributeMaxDynamicSharedMemorySize, SMEM_BLK);

    cs_kernel<<<dim3(8, 16), 256>>>(x, Wcs, csy, Wb, wblk);
    init_kernel<<<dim3(8, 16), 256>>>(csy, Wi, initrec);
    first_kernel<<<dim3(16, 16, 16), 256>>>(initrec, Wf, aM, hiA, loA);

    for (int i = 0; i < 4; i++) {
        blk_mma<false><<<dim3(64, 16), 512, SMEM_BLK>>>(hiA, loA, wblk, aB, hiB, loB);
        blk_mma<true><<<dim3(64, 16), 512, SMEM_BLK>>>(hiB, loB, wblk, aB, hiA, loA);
    }
    last_kernel<<<dim3(16, 16, 16), 256>>>(hiA, loA, initrec, Wl, out);
}

// round 14
// speedup vs baseline: 1.2345x; 1.0721x over previous
#include <cuda_runtime.h>
#include <cuda_bf16.h>
#include <cstdint>

#define HWSZ 65536
#define FEAT (16*64*HWSZ)
#define PLANE ((size_t)16*HWSZ*64)

__device__ float g_featA[FEAT];
__device__ float g_featB[FEAT];
__device__ unsigned char g_wblk[147456];   // [tap 9][co 64][K 128] bf16, swizzled

#define SA_OFF 147456
#define SLOT_SZ 16896                      // 2 planes x 66px x 128B, XOR-swizzled
#define SMEM_BLK (147456 + 4 * SLOT_SZ)    // 215,040 B

__device__ __forceinline__ float prelu_f(float v, float a) { return v >= 0.f ? v : a * v; }

__device__ __forceinline__ uint32_t smem_u32(const void* p) {
    uint32_t a;
    asm("{ .reg .u64 t; cvta.to.shared.u64 t, %1; cvt.u32.u64 %0, t; }" : "=r"(a) : "l"(p));
    return a;
}
__device__ __forceinline__ void ldsm4(uint32_t* r, uint32_t addr) {
    asm volatile("ldmatrix.sync.aligned.m8n8.x4.shared.b16 {%0,%1,%2,%3}, [%4];"
                 : "=r"(r[0]), "=r"(r[1]), "=r"(r[2]), "=r"(r[3]) : "r"(addr));
}
__device__ __forceinline__ void mma16816(float* d, const uint32_t* a, uint32_t b0, uint32_t b1) {
    asm volatile("mma.sync.aligned.m16n8k16.row.col.f32.bf16.bf16.f32 "
                 "{%0,%1,%2,%3},{%4,%5,%6,%7},{%8,%9},{%0,%1,%2,%3};"
                 : "+f"(d[0]), "+f"(d[1]), "+f"(d[2]), "+f"(d[3])
                 : "r"(a[0]), "r"(a[1]), "r"(a[2]), "r"(a[3]), "r"(b0), "r"(b1));
}
__device__ __forceinline__ void cpa16(uint32_t dst, const void* src, int sz) {
    asm volatile("cp.async.cg.shared.global [%0], [%1], 16, %2;" :: "r"(dst), "l"(src), "r"(sz));
}
__device__ __forceinline__ void cpa16f(uint32_t dst, const void* src) {
    asm volatile("cp.async.cg.shared.global [%0], [%1], 16;" :: "r"(dst), "l"(src));
}
#define CPA_COMMIT() asm volatile("cp.async.commit_group;")
#define CPA_WAIT1()  asm volatile("cp.async.wait_group 1;")
#define CPA_WAIT0()  asm volatile("cp.async.wait_group 0;")

// ---------------- CS sampling conv (fp32) + fused weight prep --------------
__global__ void cs_kernel(const float* __restrict__ x, const float* __restrict__ Wcs,
                          float* __restrict__ csy,
                          const float* __restrict__ Wb, unsigned char* __restrict__ wsp) {
    const int pg = blockIdx.x, n = blockIdx.y, f = threadIdx.x;
    {   // weight-prep slice: 128 blocks x 576 = 73,728 elems
        int bid = blockIdx.y * 8 + blockIdx.x;
        for (int i = bid * 576 + threadIdx.x; i < bid * 576 + 576; i += 256) {
            int k = i & 127, co = (i >> 7) & 63, tap = i >> 13;
            int ci = k & 63, seg = k >> 6;
            float w = Wb[co * 576 + ci * 9 + tap];
            __nv_bfloat16 h = __float2bfloat16(w);
            __nv_bfloat16 v = seg ? __float2bfloat16(w - __bfloat162float(h)) : h;
            int kb = 2 * k;
            int off = (kb & 128) | ((kb & 127) ^ ((co & 7) << 4));
            *(__nv_bfloat16*)(wsp + tap * 16384 + co * 256 + off) = v;
        }
    }
    __shared__ float sX[8][32];
    __shared__ float sW[256][33];
    float acc[8] = {};
    for (int k0 = 0; k0 < 1024; k0 += 32) {
        const int i = k0 >> 5;
        int p = threadIdx.x >> 5, kk = threadIdx.x & 31;
        sX[p][kk] = x[n * HWSZ + (pg * 32 + i) * 256 + p * 32 + kk];
        for (int e = threadIdx.x; e < 8192; e += 256)
            sW[e >> 5][e & 31] = Wcs[(e >> 5) * 1024 + k0 + (e & 31)];
        __syncthreads();
#pragma unroll
        for (int q = 0; q < 32; q++) {
            float w = sW[f][q];
#pragma unroll
            for (int pp = 0; pp < 8; pp++) acc[pp] += sX[pp][q] * w;
        }
        __syncthreads();
    }
#pragma unroll
    for (int pp = 0; pp < 8; pp++) csy[(n * 256 + f) * 64 + pg * 8 + pp] = acc[pp];
}

// ---------------- init reconstruction (fp32) -------------------------------
__global__ void init_kernel(const float* __restrict__ csy, const float* __restrict__ Wi,
                            float* __restrict__ initrec) {
    const int cb = blockIdx.x * 128, n = blockIdx.y;
    const int cg = threadIdx.x >> 3, pgl = threadIdx.x & 7;
    __shared__ float sX[32][64];
    __shared__ float sW[128][33];
    float acc[4][8] = {};
    for (int k0 = 0; k0 < 256; k0 += 32) {
        for (int e = threadIdx.x; e < 2048; e += 256)
            sX[e >> 6][e & 63] = csy[(n * 256 + k0 + (e >> 6)) * 64 + (e & 63)];
        for (int e = threadIdx.x; e < 4096; e += 256)
            sW[e >> 5][e & 31] = Wi[(cb + (e >> 5)) * 256 + k0 + (e & 31)];
        __syncthreads();
#pragma unroll
        for (int kk = 0; kk < 32; kk++) {
            float w0 = sW[cg*4+0][kk], w1 = sW[cg*4+1][kk], w2 = sW[cg*4+2][kk], w3 = sW[cg*4+3][kk];
#pragma unroll
            for (int pp = 0; pp < 8; pp++) {
                float xv = sX[kk][pgl * 8 + pp];
                acc[0][pp] += w0*xv; acc[1][pp] += w1*xv; acc[2][pp] += w2*xv; acc[3][pp] += w3*xv;
            }
        }
        __syncthreads();
    }
#pragma unroll
    for (int jc = 0; jc < 4; jc++) {
        int c = cb + cg * 4 + jc, jj = c >> 5, ii = c & 31;
#pragma unroll
        for (int pp = 0; pp < 8; pp++) {
            int pos = pgl * 8 + pp, by = pos >> 3, bx = pos & 7;
            initrec[n * HWSZ + (by * 32 + ii) * 256 + (bx * 32 + jj)] = acc[jc][pp];
        }
    }
}

// ------- first conv 1->64 + PReLU -> hi/lo bf16 planes ---------------------
__global__ void first_kernel(const float* __restrict__ initrec, const float* __restrict__ Wf,
                             const float* __restrict__ aM,
                             __nv_bfloat16* __restrict__ outH, __nv_bfloat16* __restrict__ outL) {
    const int tx = blockIdx.x, ty = blockIdx.y, n = blockIdx.z;
    __shared__ float sI[18][18];
    __shared__ float sWf[576];
    for (int e = threadIdx.x; e < 324; e += 256) {
        int yy = e / 18, xx = e % 18, gy = ty * 16 - 1 + yy, gx = tx * 16 - 1 + xx;
        sI[yy][xx] = ((unsigned)gy < 256u && (unsigned)gx < 256u) ? initrec[n * HWSZ + gy * 256 + gx] : 0.f;
    }
    for (int e = threadIdx.x; e < 576; e += 256) sWf[e] = Wf[e];
    __syncthreads();
    const float a = aM[0];
    const int co = threadIdx.x & 63, pl = threadIdx.x >> 6;
    float wr[9];
#pragma unroll
    for (int k = 0; k < 9; k++) wr[k] = sWf[co * 9 + k];
    for (int pxi = 0; pxi < 64; pxi++) {
        int px = pxi * 4 + pl, r = px >> 4, c = px & 15;
        float s = 0.f;
#pragma unroll
        for (int ky = 0; ky < 3; ky++)
#pragma unroll
            for (int kx = 0; kx < 3; kx++) s += wr[ky * 3 + kx] * sI[r + ky][c + kx];
        s = prelu_f(s, a);
        __nv_bfloat16 h = __float2bfloat16(s);
        __nv_bfloat16 l = __float2bfloat16(s - __bfloat162float(h));
        size_t ad = ((size_t)(n * HWSZ + (ty * 16 + r) * 256 + tx * 16 + c)) * 64 + co;
        outH[ad] = h;
        outL[ad] = l;
    }
}

// ---------- res-block conv 64->64: 2-row tiles, 16 warps (R10 structure) ---
// grid (64, 16): x-col = (bx&3)*64, y-group = (bx>>2)*16. 512 thr, 16 warps:
// warp = m(4, 16px) x ng(4, 16co). 4-slot row ring, XOR swizzle.
__device__ __forceinline__ void load_row(uint32_t sb, const __nv_bfloat16* inH,
                                         const __nv_bfloat16* inL, int n, int y,
                                         int x0, int slot, int tid) {
    uint32_t base = sb + SA_OFF + (uint32_t)slot * SLOT_SZ;
    for (int idx = tid; idx < 1056; idx += 512) {
        int plane = idx >= 528;
        int i2 = plane ? idx - 528 : idx;
        int px = i2 >> 3, ch = i2 & 7;
        int gx = x0 - 1 + px;
        bool ok = (unsigned)y < 256u && (unsigned)gx < 256u;
        const __nv_bfloat16* bp = plane ? inL : inH;
        const __nv_bfloat16* sp = ok ? bp + ((size_t)(n * HWSZ + y * 256 + gx)) * 64 + ch * 8 : bp;
        uint32_t dst = base + (uint32_t)plane * 8448 + (uint32_t)px * 128 +
                       (((uint32_t)ch << 4) ^ (((uint32_t)px & 7) << 4));
        cpa16(dst, sp, ok ? 16 : 0);
    }
}

template <bool RES>
__global__ void __launch_bounds__(512, 1) blk_mma(
    const __nv_bfloat16* __restrict__ inH, const __nv_bfloat16* __restrict__ inL,
    const unsigned char* __restrict__ wblk, const float* __restrict__ aB,
    __nv_bfloat16* __restrict__ outH, __nv_bfloat16* __restrict__ outL) {
    extern __shared__ unsigned char sm[];
    const uint32_t sb = smem_u32(sm);
    const int tid = threadIdx.x, w = tid >> 5, lane = tid & 31;
    const int n = blockIdx.y, x0 = (blockIdx.x & 3) * 64, y0 = (blockIdx.x >> 2) * 16;
    const int m = w & 3, ng = w >> 2;

    // Prologue: B (all taps) + rows rel 0,1,2 in group A; rel 3 in group B.
    {
        const uint4* s = (const uint4*)wblk;
        for (int i = tid; i < 9216; i += 512) cpa16f(sb + i * 16, s + i);
    }
    load_row(sb, inH, inL, n, y0 - 1, x0, 0, tid);   // rel 0
    load_row(sb, inH, inL, n, y0,     x0, 1, tid);   // rel 1
    load_row(sb, inH, inL, n, y0 + 1, x0, 2, tid);   // rel 2
    CPA_COMMIT();
    load_row(sb, inH, inL, n, y0 + 2, x0, 3, tid);   // rel 3
    CPA_COMMIT();

    // per-lane constants
    const int pxl = m * 16 + (lane & 15);
    const uint32_t h16 = ((lane >> 4) & 1) << 4;
    const int co_l = (lane & 7) + ((lane >> 4) & 1) * 8;
    const int kb_l = ((lane >> 3) & 1) * 16;
    const int sx = (lane & 7) << 4;
    uint32_t offk[8];
#pragma unroll
    for (int j = 0; j < 8; j++) {
        int kb = j * 32 + kb_l;
        offk[j] = (uint32_t)((kb & 128) | ((kb & 127) ^ sx));
    }
    const uint32_t bbase = sb + (uint32_t)(ng * 16 + co_l) * 256;
    const float a = aB[0];

    for (int t = 0; t < 8; t++) {
        uint32_t slotA[4];
#pragma unroll
        for (int j = 0; j < 4; j++)
            slotA[j] = sb + SA_OFF + (uint32_t)((2 * t + j) & 3) * SLOT_SZ;

        float acc[2][2][4];
#pragma unroll
        for (int r = 0; r < 2; r++)
#pragma unroll
            for (int i = 0; i < 2; i++)
#pragma unroll
                for (int j = 0; j < 4; j++) acc[r][i][j] = 0.f;

        CPA_WAIT1();          // rels <= 2t+2 resident; rel 2t+3 in flight
        __syncthreads();

#pragma unroll
        for (int ky = 0; ky < 3; ky++) {
            if (ky == 2) {    // rel 2t+3 first needed at j=3 (r=1, ky=2)
                CPA_WAIT0();
                __syncthreads();
            }
#pragma unroll
            for (int kx = 0; kx < 3; kx++) {
                const uint32_t px = (uint32_t)(pxl + kx);
                const uint32_t sw = (px & 7) << 4;
                const uint32_t a0 = slotA[ky + 0] + px * 128;   // row r=0
                const uint32_t a1 = slotA[ky + 1] + px * 128;   // row r=1
                const uint32_t bt = bbase + (uint32_t)(ky * 3 + kx) * 16384;
#pragma unroll
                for (int q = 0; q < 4; q++) {
                    const uint32_t off = (h16 | ((uint32_t)q << 5)) ^ sw;
                    uint32_t ah0[4], ah1[4], al0[4], al1[4], bh[4], bl[4];
                    ldsm4(ah0, a0 + off);
                    ldsm4(ah1, a1 + off);
                    ldsm4(al0, a0 + 8448 + off);
                    ldsm4(al1, a1 + 8448 + off);
                    ldsm4(bh, bt + offk[q]);
                    ldsm4(bl, bt + offk[4 + q]);
                    // wh x (xh, xl); wl x xh
                    mma16816(acc[0][0], ah0, bh[0], bh[1]);
                    mma16816(acc[0][1], ah0, bh[2], bh[3]);
                    mma16816(acc[1][0], ah1, bh[0], bh[1]);
                    mma16816(acc[1][1], ah1, bh[2], bh[3]);
                    mma16816(acc[0][0], al0, bh[0], bh[1]);
                    mma16816(acc[0][1], al0, bh[2], bh[3]);
                    mma16816(acc[1][0], al1, bh[0], bh[1]);
                    mma16816(acc[1][1], al1, bh[2], bh[3]);
                    mma16816(acc[0][0], ah0, bl[0], bl[1]);
                    mma16816(acc[0][1], ah0, bl[2], bl[3]);
                    mma16816(acc[1][0], ah1, bl[0], bl[1]);
                    mma16816(acc[1][1], ah1, bl[2], bl[3]);
                }
            }
        }
        __syncthreads();      // slab reads done

        // issue next tile's rows (rels 2t+4, 2t+5) — overlap with epilogue
        if (t < 7) {
            load_row(sb, inH, inL, n, y0 + 2 * t + 3, x0, (2 * t + 4) & 3, tid);
            CPA_COMMIT();
            load_row(sb, inH, inL, n, y0 + 2 * t + 4, x0, (2 * t + 5) & 3, tid);
            CPA_COMMIT();
        }

        // epilogue: residual + PReLU + split store (2 rows x 16px x 16co)
        const int r0 = lane >> 2;
#pragma unroll
        for (int r = 0; r < 2; r++) {
            const size_t rowbase = (size_t)(n * HWSZ + (y0 + 2 * t + r) * 256 + x0 + m * 16);
#pragma unroll
            for (int h = 0; h < 2; h++) {
                size_t pa = (rowbase + r0 + h * 8) * 64 + ng * 16 + (lane & 3) * 2;
#pragma unroll
                for (int q = 0; q < 2; q++) {
                    size_t ad = pa + q * 8;
                    float v0 = acc[r][q][h * 2 + 0], v1 = acc[r][q][h * 2 + 1];
                    if (RES) {
                        uint32_t h2 = *(const uint32_t*)(outH + ad);
                        uint32_t l2 = *(const uint32_t*)(outL + ad);
                        v0 += __bfloat162float(__ushort_as_bfloat16((unsigned short)(h2 & 0xffff))) +
                              __bfloat162float(__ushort_as_bfloat16((unsigned short)(l2 & 0xffff)));
                        v1 += __bfloat162float(__ushort_as_bfloat16((unsigned short)(h2 >> 16))) +
                              __bfloat162float(__ushort_as_bfloat16((unsigned short)(l2 >> 16)));
                    }
                    v0 = prelu_f(v0, a);
                    v1 = prelu_f(v1, a);
                    __nv_bfloat16 h0 = __float2bfloat16(v0), h1 = __float2bfloat16(v1);
                    __nv_bfloat16 l0 = __float2bfloat16(v0 - __bfloat162float(h0));
                    __nv_bfloat16 l1 = __float2bfloat16(v1 - __bfloat162float(h1));
                    *(uint32_t*)(outH + ad) = (uint32_t)__bfloat16_as_ushort(h0) |
                                              ((uint32_t)__bfloat16_as_ushort(h1) << 16);
                    *(uint32_t*)(outL + ad) = (uint32_t)__bfloat16_as_ushort(l0) |
                                              ((uint32_t)__bfloat16_as_ushort(l1) << 16);
                }
            }
        }
        __syncthreads();      // epilogue/residual reads done before slots reused
    }
}

// --------- last conv: (feat planes + initrec) -> 1 channel, vectorized -----
__global__ void last_kernel(const __nv_bfloat16* __restrict__ featH,
                            const __nv_bfloat16* __restrict__ featL,
                            const float* __restrict__ initrec,
                            const float* __restrict__ Wl, float* __restrict__ out) {
    const int tx = blockIdx.x, ty = blockIdx.y, n = blockIdx.z;
    __shared__ float sInit[18][18];
    __shared__ float sIn[8][18][20];
    __shared__ float sWl[576];
    for (int e = threadIdx.x; e < 324; e += 256) {
        int yy = e / 18, xx = e % 18, gy = ty * 16 - 1 + yy, gx = tx * 16 - 1 + xx;
        sInit[yy][xx] = ((unsigned)gy < 256u && (unsigned)gx < 256u) ? initrec[n * HWSZ + gy * 256 + gx] : 0.f;
    }
    for (int e = threadIdx.x; e < 576; e += 256) sWl[e] = Wl[e];
    __syncthreads();
    const int r = threadIdx.x >> 4, c = threadIdx.x & 15;
    float acc = 0.f;
    for (int ci0 = 0; ci0 < 64; ci0 += 8) {
        for (int e = threadIdx.x; e < 324; e += 256) {
            int yy = e / 18, xx = e % 18;
            int gy = ty * 16 - 1 + yy, gx = tx * 16 - 1 + xx;
            float init = sInit[yy][xx];
            if ((unsigned)gy < 256u && (unsigned)gx < 256u) {
                size_t ad = (size_t)(n * HWSZ + gy * 256 + gx) * 64 + ci0;
                uint4 h4 = *(const uint4*)(featH + ad);
                uint4 l4 = *(const uint4*)(featL + ad);
                const uint32_t* hp = &h4.x;
                const uint32_t* lp = &l4.x;
#pragma unroll
                for (int p = 0; p < 4; p++) {
                    float v0 = __bfloat162float(__ushort_as_bfloat16((unsigned short)(hp[p] & 0xffff))) +
                               __bfloat162float(__ushort_as_bfloat16((unsigned short)(lp[p] & 0xffff)));
                    float v1 = __bfloat162float(__ushort_as_bfloat16((unsigned short)(hp[p] >> 16))) +
                               __bfloat162float(__ushort_as_bfloat16((unsigned short)(lp[p] >> 16)));
                    sIn[2 * p + 0][yy][xx] = v0 + init;
                    sIn[2 * p + 1][yy][xx] = v1 + init;
                }
            } else {
#pragma unroll
                for (int j = 0; j < 8; j++) sIn[j][yy][xx] = init;
            }
        }
        __syncthreads();
#pragma unroll 1
        for (int ci = 0; ci < 8; ci++)
#pragma unroll
            for (int ky = 0; ky < 3; ky++)
#pragma unroll
                for (int kx = 0; kx < 3; kx++)
                    acc += sIn[ci][r + ky][c + kx] * sWl[(ci0 + ci) * 9 + ky * 3 + kx];
        __syncthreads();
    }
    out[n * HWSZ + (ty * 16 + r) * 256 + (tx * 16 + c)] = acc;
}

// ---------------------------------------------------------------------------
extern "C" void kernel_launch(void* const* d_in, const int* in_sizes, int n_in,
                              void* d_out, int out_size) {
    (void)in_sizes; (void)n_in; (void)out_size;
    const float* x   = (const float*)d_in[0];
    const float* Wcs = (const float*)d_in[1];
    const float* Wi  = (const float*)d_in[2];
    const float* Wf  = (const float*)d_in[3];
    const float* Wb  = (const float*)d_in[4];
    const float* Wl  = (const float*)d_in[5];
    const float* aM  = (const float*)d_in[6];
    const float* aB  = (const float*)d_in[7];

    float* out     = (float*)d_out;
    float* csy     = out + 16 * HWSZ;
    float* initrec = csy + 16 * 256 * 64;

    void *pA = nullptr, *pB = nullptr, *pW = nullptr;
    cudaGetSymbolAddress(&pA, g_featA);
    cudaGetSymbolAddress(&pB, g_featB);
    cudaGetSymbolAddress(&pW, g_wblk);
    __nv_bfloat16* hiA = (__nv_bfloat16*)pA;
    __nv_bfloat16* loA = hiA + PLANE;
    __nv_bfloat16* hiB = (__nv_bfloat16*)pB;
    __nv_bfloat16* loB = hiB + PLANE;
    unsigned char* wblk = (unsigned char*)pW;

    cudaFuncSetAttribute(blk_mma<false>, cudaFuncAttributeMaxDynamicSharedMemorySize, SMEM_BLK);
    cudaFuncSetAttribute(blk_mma<true>,  cudaFuncAttributeMaxDynamicSharedMemorySize, SMEM_BLK);

    cs_kernel<<<dim3(8, 16), 256>>>(x, Wcs, csy, Wb, wblk);
    init_kernel<<<dim3(8, 16), 256>>>(csy, Wi, initrec);
    first_kernel<<<dim3(16, 16, 16), 256>>>(initrec, Wf, aM, hiA, loA);

    for (int i = 0; i < 4; i++) {
        blk_mma<false><<<dim3(64, 16), 512, SMEM_BLK>>>(hiA, loA, wblk, aB, hiB, loB);
        blk_mma<true><<<dim3(64, 16), 512, SMEM_BLK>>>(hiB, loB, wblk, aB, hiA, loA);
    }
    last_kernel<<<dim3(16, 16, 16), 256>>>(hiA, loA, initrec, Wl, out);
}

// round 15
// speedup vs baseline: 1.4477x; 1.1727x over previous
#include <cuda_runtime.h>
#include <cuda_bf16.h>
#include <cstdint>

#define HWSZ 65536
#define FEAT (16*64*HWSZ)
#define PLANE ((size_t)16*HWSZ*64)

__device__ float g_featA[FEAT];
__device__ float g_featB[FEAT];
__device__ unsigned char g_wblk[147456];   // [tap 9][co 64][K 128] bf16, swizzled

#define SA_OFF 147456
#define SLOT_SZ 16896                      // 2 planes x 66px x 128B, XOR-swizzled
#define SMEM_BLK (147456 + 4 * SLOT_SZ)    // 215,040 B

__device__ __forceinline__ float prelu_f(float v, float a) { return v >= 0.f ? v : a * v; }

__device__ __forceinline__ uint32_t smem_u32(const void* p) {
    uint32_t a;
    asm("{ .reg .u64 t; cvta.to.shared.u64 t, %1; cvt.u32.u64 %0, t; }" : "=r"(a) : "l"(p));
    return a;
}
__device__ __forceinline__ void ldsm4(uint32_t* r, uint32_t addr) {
    asm volatile("ldmatrix.sync.aligned.m8n8.x4.shared.b16 {%0,%1,%2,%3}, [%4];"
                 : "=r"(r[0]), "=r"(r[1]), "=r"(r[2]), "=r"(r[3]) : "r"(addr));
}
__device__ __forceinline__ void mma16816(float* d, const uint32_t* a, uint32_t b0, uint32_t b1) {
    asm volatile("mma.sync.aligned.m16n8k16.row.col.f32.bf16.bf16.f32 "
                 "{%0,%1,%2,%3},{%4,%5,%6,%7},{%8,%9},{%0,%1,%2,%3};"
                 : "+f"(d[0]), "+f"(d[1]), "+f"(d[2]), "+f"(d[3])
                 : "r"(a[0]), "r"(a[1]), "r"(a[2]), "r"(a[3]), "r"(b0), "r"(b1));
}
__device__ __forceinline__ void cpa16(uint32_t dst, const void* src, int sz) {
    asm volatile("cp.async.cg.shared.global [%0], [%1], 16, %2;" :: "r"(dst), "l"(src), "r"(sz));
}
__device__ __forceinline__ void cpa16f(uint32_t dst, const void* src) {
    asm volatile("cp.async.cg.shared.global [%0], [%1], 16;" :: "r"(dst), "l"(src));
}
#define CPA_COMMIT() asm volatile("cp.async.commit_group;")
#define CPA_WAIT1()  asm volatile("cp.async.wait_group 1;")
#define CPA_WAIT0()  asm volatile("cp.async.wait_group 0;")

// ---------------- CS sampling conv (fp32) + fused weight prep --------------
__global__ void cs_kernel(const float* __restrict__ x, const float* __restrict__ Wcs,
                          float* __restrict__ csy,
                          const float* __restrict__ Wb, unsigned char* __restrict__ wsp) {
    const int pg = blockIdx.x, n = blockIdx.y, f = threadIdx.x;
    {   // weight-prep slice: 128 blocks x 576 = 73,728 elems
        int bid = blockIdx.y * 8 + blockIdx.x;
        for (int i = bid * 576 + threadIdx.x; i < bid * 576 + 576; i += 256) {
            int k = i & 127, co = (i >> 7) & 63, tap = i >> 13;
            int ci = k & 63, seg = k >> 6;
            float w = Wb[co * 576 + ci * 9 + tap];
            __nv_bfloat16 h = __float2bfloat16(w);
            __nv_bfloat16 v = seg ? __float2bfloat16(w - __bfloat162float(h)) : h;
            int kb = 2 * k;
            int off = (kb & 128) | ((kb & 127) ^ ((co & 7) << 4));
            *(__nv_bfloat16*)(wsp + tap * 16384 + co * 256 + off) = v;
        }
    }
    __shared__ float sX[8][32];
    __shared__ float sW[256][33];
    float acc[8] = {};
    for (int k0 = 0; k0 < 1024; k0 += 32) {
        const int i = k0 >> 5;
        int p = threadIdx.x >> 5, kk = threadIdx.x & 31;
        sX[p][kk] = x[n * HWSZ + (pg * 32 + i) * 256 + p * 32 + kk];
        for (int e = threadIdx.x; e < 8192; e += 256)
            sW[e >> 5][e & 31] = Wcs[(e >> 5) * 1024 + k0 + (e & 31)];
        __syncthreads();
#pragma unroll
        for (int q = 0; q < 32; q++) {
            float w = sW[f][q];
#pragma unroll
            for (int pp = 0; pp < 8; pp++) acc[pp] += sX[pp][q] * w;
        }
        __syncthreads();
    }
#pragma unroll
    for (int pp = 0; pp < 8; pp++) csy[(n * 256 + f) * 64 + pg * 8 + pp] = acc[pp];
}

// ---------------- init reconstruction (fp32) -------------------------------
__global__ void init_kernel(const float* __restrict__ csy, const float* __restrict__ Wi,
                            float* __restrict__ initrec) {
    const int cb = blockIdx.x * 128, n = blockIdx.y;
    const int cg = threadIdx.x >> 3, pgl = threadIdx.x & 7;
    __shared__ float sX[32][64];
    __shared__ float sW[128][33];
    float acc[4][8] = {};
    for (int k0 = 0; k0 < 256; k0 += 32) {
        for (int e = threadIdx.x; e < 2048; e += 256)
            sX[e >> 6][e & 63] = csy[(n * 256 + k0 + (e >> 6)) * 64 + (e & 63)];
        for (int e = threadIdx.x; e < 4096; e += 256)
            sW[e >> 5][e & 31] = Wi[(cb + (e >> 5)) * 256 + k0 + (e & 31)];
        __syncthreads();
#pragma unroll
        for (int kk = 0; kk < 32; kk++) {
            float w0 = sW[cg*4+0][kk], w1 = sW[cg*4+1][kk], w2 = sW[cg*4+2][kk], w3 = sW[cg*4+3][kk];
#pragma unroll
            for (int pp = 0; pp < 8; pp++) {
                float xv = sX[kk][pgl * 8 + pp];
                acc[0][pp] += w0*xv; acc[1][pp] += w1*xv; acc[2][pp] += w2*xv; acc[3][pp] += w3*xv;
            }
        }
        __syncthreads();
    }
#pragma unroll
    for (int jc = 0; jc < 4; jc++) {
        int c = cb + cg * 4 + jc, jj = c >> 5, ii = c & 31;
#pragma unroll
        for (int pp = 0; pp < 8; pp++) {
            int pos = pgl * 8 + pp, by = pos >> 3, bx = pos & 7;
            initrec[n * HWSZ + (by * 32 + ii) * 256 + (bx * 32 + jj)] = acc[jc][pp];
        }
    }
}

// ---- tiny dummy: shifts the ncu capture slot onto blk_mma<true> -----------
__global__ void dummy_kernel() {}

// ------- first conv 1->64 + PReLU -> hi/lo bf16 planes (coalesced) ---------
__global__ void first_kernel(const float* __restrict__ initrec, const float* __restrict__ Wf,
                             const float* __restrict__ aM,
                             __nv_bfloat16* __restrict__ outH, __nv_bfloat16* __restrict__ outL) {
    const int tx = blockIdx.x, ty = blockIdx.y, n = blockIdx.z;
    __shared__ float sI[18][18];
    __shared__ float sWf[576];
    for (int e = threadIdx.x; e < 324; e += 256) {
        int yy = e / 18, xx = e % 18, gy = ty * 16 - 1 + yy, gx = tx * 16 - 1 + xx;
        sI[yy][xx] = ((unsigned)gy < 256u && (unsigned)gx < 256u) ? initrec[n * HWSZ + gy * 256 + gx] : 0.f;
    }
    for (int e = threadIdx.x; e < 576; e += 256) sWf[e] = Wf[e];
    __syncthreads();
    const float a = aM[0];
    // e = px*8 + co8: thread block covers 2048 uint4 stores per plane, coalesced.
    for (int e = threadIdx.x; e < 2048; e += 256) {
        int px = e >> 3, co8 = e & 7;
        int r = px >> 4, c = px & 15;
        uint32_t hw[4], lw[4];
#pragma unroll
        for (int j = 0; j < 4; j++) {
            float s[2];
#pragma unroll
            for (int u = 0; u < 2; u++) {
                int co = co8 * 8 + j * 2 + u;
                float acc = 0.f;
#pragma unroll
                for (int ky = 0; ky < 3; ky++)
#pragma unroll
                    for (int kx = 0; kx < 3; kx++)
                        acc += sWf[co * 9 + ky * 3 + kx] * sI[r + ky][c + kx];
                s[u] = prelu_f(acc, a);
            }
            __nv_bfloat16 h0 = __float2bfloat16(s[0]), h1 = __float2bfloat16(s[1]);
            __nv_bfloat16 l0 = __float2bfloat16(s[0] - __bfloat162float(h0));
            __nv_bfloat16 l1 = __float2bfloat16(s[1] - __bfloat162float(h1));
            hw[j] = (uint32_t)__bfloat16_as_ushort(h0) | ((uint32_t)__bfloat16_as_ushort(h1) << 16);
            lw[j] = (uint32_t)__bfloat16_as_ushort(l0) | ((uint32_t)__bfloat16_as_ushort(l1) << 16);
        }
        size_t ad = ((size_t)(n * HWSZ + (ty * 16 + r) * 256 + tx * 16 + c)) * 64 + co8 * 8;
        *(uint4*)(outH + ad) = make_uint4(hw[0], hw[1], hw[2], hw[3]);
        *(uint4*)(outL + ad) = make_uint4(lw[0], lw[1], lw[2], lw[3]);
    }
}

// ---------- res-block conv 64->64: 2-row tiles, 16 warps (R10 structure) ---
__device__ __forceinline__ void load_row(uint32_t sb, const __nv_bfloat16* inH,
                                         const __nv_bfloat16* inL, int n, int y,
                                         int x0, int slot, int tid) {
    uint32_t base = sb + SA_OFF + (uint32_t)slot * SLOT_SZ;
    for (int idx = tid; idx < 1056; idx += 512) {
        int plane = idx >= 528;
        int i2 = plane ? idx - 528 : idx;
        int px = i2 >> 3, ch = i2 & 7;
        int gx = x0 - 1 + px;
        bool ok = (unsigned)y < 256u && (unsigned)gx < 256u;
        const __nv_bfloat16* bp = plane ? inL : inH;
        const __nv_bfloat16* sp = ok ? bp + ((size_t)(n * HWSZ + y * 256 + gx)) * 64 + ch * 8 : bp;
        uint32_t dst = base + (uint32_t)plane * 8448 + (uint32_t)px * 128 +
                       (((uint32_t)ch << 4) ^ (((uint32_t)px & 7) << 4));
        cpa16(dst, sp, ok ? 16 : 0);
    }
}

template <bool RES>
__global__ void __launch_bounds__(512, 1) blk_mma(
    const __nv_bfloat16* __restrict__ inH, const __nv_bfloat16* __restrict__ inL,
    const unsigned char* __restrict__ wblk, const float* __restrict__ aB,
    __nv_bfloat16* __restrict__ outH, __nv_bfloat16* __restrict__ outL) {
    extern __shared__ unsigned char sm[];
    const uint32_t sb = smem_u32(sm);
    const int tid = threadIdx.x, w = tid >> 5, lane = tid & 31;
    const int n = blockIdx.y, x0 = (blockIdx.x & 3) * 64, y0 = (blockIdx.x >> 2) * 16;
    const int m = w & 3, ng = w >> 2;

    // Prologue: B (all taps) + rows rel 0,1,2 in group A; rel 3 in group B.
    {
        const uint4* s = (const uint4*)wblk;
        for (int i = tid; i < 9216; i += 512) cpa16f(sb + i * 16, s + i);
    }
    load_row(sb, inH, inL, n, y0 - 1, x0, 0, tid);   // rel 0
    load_row(sb, inH, inL, n, y0,     x0, 1, tid);   // rel 1
    load_row(sb, inH, inL, n, y0 + 1, x0, 2, tid);   // rel 2
    CPA_COMMIT();
    load_row(sb, inH, inL, n, y0 + 2, x0, 3, tid);   // rel 3
    CPA_COMMIT();

    // per-lane constants
    const int pxl = m * 16 + (lane & 15);
    const uint32_t h16 = ((lane >> 4) & 1) << 4;
    const int co_l = (lane & 7) + ((lane >> 4) & 1) * 8;
    const int kb_l = ((lane >> 3) & 1) * 16;
    const int sx = (lane & 7) << 4;
    uint32_t offk[8];
#pragma unroll
    for (int j = 0; j < 8; j++) {
        int kb = j * 32 + kb_l;
        offk[j] = (uint32_t)((kb & 128) | ((kb & 127) ^ sx));
    }
    const uint32_t bbase = sb + (uint32_t)(ng * 16 + co_l) * 256;
    const float a = aB[0];

    for (int t = 0; t < 8; t++) {
        uint32_t slotA[4];
#pragma unroll
        for (int j = 0; j < 4; j++)
            slotA[j] = sb + SA_OFF + (uint32_t)((2 * t + j) & 3) * SLOT_SZ;

        float acc[2][2][4];
#pragma unroll
        for (int r = 0; r < 2; r++)
#pragma unroll
            for (int i = 0; i < 2; i++)
#pragma unroll
                for (int j = 0; j < 4; j++) acc[r][i][j] = 0.f;

        CPA_WAIT1();          // rels <= 2t+2 resident; rel 2t+3 in flight
        __syncthreads();

#pragma unroll
        for (int ky = 0; ky < 3; ky++) {
            if (ky == 2) {    // rel 2t+3 first needed at j=3 (r=1, ky=2)
                CPA_WAIT0();
                __syncthreads();
            }
#pragma unroll
            for (int kx = 0; kx < 3; kx++) {
                const uint32_t px = (uint32_t)(pxl + kx);
                const uint32_t sw = (px & 7) << 4;
                const uint32_t a0 = slotA[ky + 0] + px * 128;   // row r=0
                const uint32_t a1 = slotA[ky + 1] + px * 128;   // row r=1
                const uint32_t bt = bbase + (uint32_t)(ky * 3 + kx) * 16384;
#pragma unroll
                for (int q = 0; q < 4; q++) {
                    const uint32_t off = (h16 | ((uint32_t)q << 5)) ^ sw;
                    uint32_t ah0[4], ah1[4], al0[4], al1[4], bh[4], bl[4];
                    ldsm4(ah0, a0 + off);
                    ldsm4(ah1, a1 + off);
                    ldsm4(al0, a0 + 8448 + off);
                    ldsm4(al1, a1 + 8448 + off);
                    ldsm4(bh, bt + offk[q]);
                    ldsm4(bl, bt + offk[4 + q]);
                    // wh x (xh, xl); wl x xh
                    mma16816(acc[0][0], ah0, bh[0], bh[1]);
                    mma16816(acc[0][1], ah0, bh[2], bh[3]);
                    mma16816(acc[1][0], ah1, bh[0], bh[1]);
                    mma16816(acc[1][1], ah1, bh[2], bh[3]);
                    mma16816(acc[0][0], al0, bh[0], bh[1]);
                    mma16816(acc[0][1], al0, bh[2], bh[3]);
                    mma16816(acc[1][0], al1, bh[0], bh[1]);
                    mma16816(acc[1][1], al1, bh[2], bh[3]);
                    mma16816(acc[0][0], ah0, bl[0], bl[1]);
                    mma16816(acc[0][1], ah0, bl[2], bl[3]);
                    mma16816(acc[1][0], ah1, bl[0], bl[1]);
                    mma16816(acc[1][1], ah1, bl[2], bl[3]);
                }
            }
        }
        __syncthreads();      // slab reads done

        // issue next tile's rows (rels 2t+4, 2t+5) — overlap with epilogue
        if (t < 7) {
            load_row(sb, inH, inL, n, y0 + 2 * t + 3, x0, (2 * t + 4) & 3, tid);
            CPA_COMMIT();
            load_row(sb, inH, inL, n, y0 + 2 * t + 4, x0, (2 * t + 5) & 3, tid);
            CPA_COMMIT();
        }

        // epilogue: residual (batched, MLP=16) + PReLU + split store
        const int r0 = lane >> 2;
        size_t ads[2][2][2];
#pragma unroll
        for (int r = 0; r < 2; r++) {
            const size_t rowbase = (size_t)(n * HWSZ + (y0 + 2 * t + r) * 256 + x0 + m * 16);
#pragma unroll
            for (int h = 0; h < 2; h++)
#pragma unroll
                for (int q = 0; q < 2; q++)
                    ads[r][h][q] = (rowbase + r0 + h * 8) * 64 + ng * 16 + (lane & 3) * 2 + q * 8;
        }
        uint32_t rh[8], rl[8];
        if (RES) {
#pragma unroll
            for (int r = 0; r < 2; r++)
#pragma unroll
                for (int h = 0; h < 2; h++)
#pragma unroll
                    for (int q = 0; q < 2; q++) {
                        int i = r * 4 + h * 2 + q;
                        rh[i] = *(const uint32_t*)(outH + ads[r][h][q]);
                        rl[i] = *(const uint32_t*)(outL + ads[r][h][q]);
                    }
        }
#pragma unroll
        for (int r = 0; r < 2; r++)
#pragma unroll
            for (int h = 0; h < 2; h++)
#pragma unroll
                for (int q = 0; q < 2; q++) {
                    int i = r * 4 + h * 2 + q;
                    size_t ad = ads[r][h][q];
                    float v0 = acc[r][q][h * 2 + 0], v1 = acc[r][q][h * 2 + 1];
                    if (RES) {
                        v0 += __bfloat162float(__ushort_as_bfloat16((unsigned short)(rh[i] & 0xffff))) +
                              __bfloat162float(__ushort_as_bfloat16((unsigned short)(rl[i] & 0xffff)));
                        v1 += __bfloat162float(__ushort_as_bfloat16((unsigned short)(rh[i] >> 16))) +
                              __bfloat162float(__ushort_as_bfloat16((unsigned short)(rl[i] >> 16)));
                    }
                    v0 = prelu_f(v0, a);
                    v1 = prelu_f(v1, a);
                    __nv_bfloat16 h0 = __float2bfloat16(v0), h1 = __float2bfloat16(v1);
                    __nv_bfloat16 l0 = __float2bfloat16(v0 - __bfloat162float(h0));
                    __nv_bfloat16 l1 = __float2bfloat16(v1 - __bfloat162float(h1));
                    *(uint32_t*)(outH + ad) = (uint32_t)__bfloat16_as_ushort(h0) |
                                              ((uint32_t)__bfloat16_as_ushort(h1) << 16);
                    *(uint32_t*)(outL + ad) = (uint32_t)__bfloat16_as_ushort(l0) |
                                              ((uint32_t)__bfloat16_as_ushort(l1) << 16);
                }
        // no tail sync: next tile's CPA_WAIT1 + __syncthreads provides ordering
    }
}

// --------- last conv: (feat planes + initrec) -> 1 channel, vectorized -----
__global__ void last_kernel(const __nv_bfloat16* __restrict__ featH,
                            const __nv_bfloat16* __restrict__ featL,
                            const float* __restrict__ initrec,
                            const float* __restrict__ Wl, float* __restrict__ out) {
    const int tx = blockIdx.x, ty = blockIdx.y, n = blockIdx.z;
    __shared__ float sInit[18][18];
    __shared__ float sIn[8][18][20];
    __shared__ float sWl[576];
    for (int e = threadIdx.x; e < 324; e += 256) {
        int yy = e / 18, xx = e % 18, gy = ty * 16 - 1 + yy, gx = tx * 16 - 1 + xx;
        sInit[yy][xx] = ((unsigned)gy < 256u && (unsigned)gx < 256u) ? initrec[n * HWSZ + gy * 256 + gx] : 0.f;
    }
    for (int e = threadIdx.x; e < 576; e += 256) sWl[e] = Wl[e];
    __syncthreads();
    const int r = threadIdx.x >> 4, c = threadIdx.x & 15;
    float acc = 0.f;
    for (int ci0 = 0; ci0 < 64; ci0 += 8) {
        for (int e = threadIdx.x; e < 324; e += 256) {
            int yy = e / 18, xx = e % 18;
            int gy = ty * 16 - 1 + yy, gx = tx * 16 - 1 + xx;
            float init = sInit[yy][xx];
            if ((unsigned)gy < 256u && (unsigned)gx < 256u) {
                size_t ad = (size_t)(n * HWSZ + gy * 256 + gx) * 64 + ci0;
                uint4 h4 = *(const uint4*)(featH + ad);
                uint4 l4 = *(const uint4*)(featL + ad);
                const uint32_t* hp = &h4.x;
                const uint32_t* lp = &l4.x;
#pragma unroll
                for (int p = 0; p < 4; p++) {
                    float v0 = __bfloat162float(__ushort_as_bfloat16((unsigned short)(hp[p] & 0xffff))) +
                               __bfloat162float(__ushort_as_bfloat16((unsigned short)(lp[p] & 0xffff)));
                    float v1 = __bfloat162float(__ushort_as_bfloat16((unsigned short)(hp[p] >> 16))) +
                               __bfloat162float(__ushort_as_bfloat16((unsigned short)(lp[p] >> 16)));
                    sIn[2 * p + 0][yy][xx] = v0 + init;
                    sIn[2 * p + 1][yy][xx] = v1 + init;
                }
            } else {
#pragma unroll
                for (int j = 0; j < 8; j++) sIn[j][yy][xx] = init;
            }
        }
        __syncthreads();
#pragma unroll 1
        for (int ci = 0; ci < 8; ci++)
#pragma unroll
            for (int ky = 0; ky < 3; ky++)
#pragma unroll
                for (int kx = 0; kx < 3; kx++)
                    acc += sIn[ci][r + ky][c + kx] * sWl[(ci0 + ci) * 9 + ky * 3 + kx];
        __syncthreads();
    }
    out[n * HWSZ + (ty * 16 + r) * 256 + (tx * 16 + c)] = acc;
}

// ---------------------------------------------------------------------------
extern "C" void kernel_launch(void* const* d_in, const int* in_sizes, int n_in,
                              void* d_out, int out_size) {
    (void)in_sizes; (void)n_in; (void)out_size;
    const float* x   = (const float*)d_in[0];
    const float* Wcs = (const float*)d_in[1];
    const float* Wi  = (const float*)d_in[2];
    const float* Wf  = (const float*)d_in[3];
    const float* Wb  = (const float*)d_in[4];
    const float* Wl  = (const float*)d_in[5];
    const float* aM  = (const float*)d_in[6];
    const float* aB  = (const float*)d_in[7];

    float* out     = (float*)d_out;
    float* csy     = out + 16 * HWSZ;
    float* initrec = csy + 16 * 256 * 64;

    void *pA = nullptr, *pB = nullptr, *pW = nullptr;
    cudaGetSymbolAddress(&pA, g_featA);
    cudaGetSymbolAddress(&pB, g_featB);
    cudaGetSymbolAddress(&pW, g_wblk);
    __nv_bfloat16* hiA = (__nv_bfloat16*)pA;
    __nv_bfloat16* loA = hiA + PLANE;
    __nv_bfloat16* hiB = (__nv_bfloat16*)pB;
    __nv_bfloat16* loB = hiB + PLANE;
    unsigned char* wblk = (unsigned char*)pW;

    cudaFuncSetAttribute(blk_mma<false>, cudaFuncAttributeMaxDynamicSharedMemorySize, SMEM_BLK);
    cudaFuncSetAttribute(blk_mma<true>,  cudaFuncAttributeMaxDynamicSharedMemorySize, SMEM_BLK);

    cs_kernel<<<dim3(8, 16), 256>>>(x, Wcs, csy, Wb, wblk);
    init_kernel<<<dim3(8, 16), 256>>>(csy, Wi, initrec);
    dummy_kernel<<<1, 32>>>();   // shifts ncu capture (-s 5 -c 1) onto blk_mma<true>
    first_kernel<<<dim3(16, 16, 16), 256>>>(initrec, Wf, aM, hiA, loA);

    for (int i = 0; i < 4; i++) {
        blk_mma<false><<<dim3(64, 16), 512, SMEM_BLK>>>(hiA, loA, wblk, aB, hiB, loB);
        blk_mma<true><<<dim3(64, 16), 512, SMEM_BLK>>>(hiB, loB, wblk, aB, hiA, loA);
    }
    last_kernel<<<dim3(16, 16, 16), 256>>>(hiA, loA, initrec, Wl, out);
}

// round 16
// speedup vs baseline: 1.5194x; 1.0495x over previous
#include <cuda_runtime.h>
#include <cuda_bf16.h>
#include <cstdint>

#define HWSZ 65536
#define FEAT (16*64*HWSZ)
#define PLANE ((size_t)16*HWSZ*64)

__device__ float g_featA[FEAT];
__device__ float g_featB[FEAT];
__device__ unsigned char g_wblk[147456];   // [tap 9][co 64][K 128] bf16, swizzled

#define SA_OFF 147456
#define SLOT_SZ 16896                      // 2 planes x 66px x 128B, XOR-swizzled
#define SMEM_BLK (147456 + 4 * SLOT_SZ)    // 215,040 B

__device__ __forceinline__ float prelu_f(float v, float a) { return v >= 0.f ? v : a * v; }

__device__ __forceinline__ uint32_t smem_u32(const void* p) {
    uint32_t a;
    asm("{ .reg .u64 t; cvta.to.shared.u64 t, %1; cvt.u32.u64 %0, t; }" : "=r"(a) : "l"(p));
    return a;
}
__device__ __forceinline__ void ldsm4(uint32_t* r, uint32_t addr) {
    asm volatile("ldmatrix.sync.aligned.m8n8.x4.shared.b16 {%0,%1,%2,%3}, [%4];"
                 : "=r"(r[0]), "=r"(r[1]), "=r"(r[2]), "=r"(r[3]) : "r"(addr));
}
__device__ __forceinline__ void mma16816(float* d, const uint32_t* a, uint32_t b0, uint32_t b1) {
    asm volatile("mma.sync.aligned.m16n8k16.row.col.f32.bf16.bf16.f32 "
                 "{%0,%1,%2,%3},{%4,%5,%6,%7},{%8,%9},{%0,%1,%2,%3};"
                 : "+f"(d[0]), "+f"(d[1]), "+f"(d[2]), "+f"(d[3])
                 : "r"(a[0]), "r"(a[1]), "r"(a[2]), "r"(a[3]), "r"(b0), "r"(b1));
}
__device__ __forceinline__ void cpa16(uint32_t dst, const void* src, int sz) {
    asm volatile("cp.async.cg.shared.global [%0], [%1], 16, %2;" :: "r"(dst), "l"(src), "r"(sz));
}
__device__ __forceinline__ void cpa16f(uint32_t dst, const void* src) {
    asm volatile("cp.async.cg.shared.global [%0], [%1], 16;" :: "r"(dst), "l"(src));
}
#define CPA_COMMIT() asm volatile("cp.async.commit_group;")
#define CPA_WAIT1()  asm volatile("cp.async.wait_group 1;")
#define CPA_WAIT0()  asm volatile("cp.async.wait_group 0;")

// ---------------- CS sampling conv (fp32) + fused weight prep --------------
__global__ void cs_kernel(const float* __restrict__ x, const float* __restrict__ Wcs,
                          float* __restrict__ csy,
                          const float* __restrict__ Wb, unsigned char* __restrict__ wsp) {
    const int pg = blockIdx.x, n = blockIdx.y, f = threadIdx.x;
    {   // weight-prep slice: 128 blocks x 576 = 73,728 elems
        int bid = blockIdx.y * 8 + blockIdx.x;
        for (int i = bid * 576 + threadIdx.x; i < bid * 576 + 576; i += 256) {
            int k = i & 127, co = (i >> 7) & 63, tap = i >> 13;
            int ci = k & 63, seg = k >> 6;
            float w = Wb[co * 576 + ci * 9 + tap];
            __nv_bfloat16 h = __float2bfloat16(w);
            __nv_bfloat16 v = seg ? __float2bfloat16(w - __bfloat162float(h)) : h;
            int kb = 2 * k;
            int off = (kb & 128) | ((kb & 127) ^ ((co & 7) << 4));
            *(__nv_bfloat16*)(wsp + tap * 16384 + co * 256 + off) = v;
        }
    }
    __shared__ float sX[8][32];
    __shared__ float sW[256][33];
    float acc[8] = {};
    for (int k0 = 0; k0 < 1024; k0 += 32) {
        const int i = k0 >> 5;
        int p = threadIdx.x >> 5, kk = threadIdx.x & 31;
        sX[p][kk] = x[n * HWSZ + (pg * 32 + i) * 256 + p * 32 + kk];
        for (int e = threadIdx.x; e < 8192; e += 256)
            sW[e >> 5][e & 31] = Wcs[(e >> 5) * 1024 + k0 + (e & 31)];
        __syncthreads();
#pragma unroll
        for (int q = 0; q < 32; q++) {
            float w = sW[f][q];
#pragma unroll
            for (int pp = 0; pp < 8; pp++) acc[pp] += sX[pp][q] * w;
        }
        __syncthreads();
    }
#pragma unroll
    for (int pp = 0; pp < 8; pp++) csy[(n * 256 + f) * 64 + pg * 8 + pp] = acc[pp];
}

// ---------------- init reconstruction (fp32) -------------------------------
__global__ void init_kernel(const float* __restrict__ csy, const float* __restrict__ Wi,
                            float* __restrict__ initrec) {
    const int cb = blockIdx.x * 128, n = blockIdx.y;
    const int cg = threadIdx.x >> 3, pgl = threadIdx.x & 7;
    __shared__ float sX[32][64];
    __shared__ float sW[128][33];
    float acc[4][8] = {};
    for (int k0 = 0; k0 < 256; k0 += 32) {
        for (int e = threadIdx.x; e < 2048; e += 256)
            sX[e >> 6][e & 63] = csy[(n * 256 + k0 + (e >> 6)) * 64 + (e & 63)];
        for (int e = threadIdx.x; e < 4096; e += 256)
            sW[e >> 5][e & 31] = Wi[(cb + (e >> 5)) * 256 + k0 + (e & 31)];
        __syncthreads();
#pragma unroll
        for (int kk = 0; kk < 32; kk++) {
            float w0 = sW[cg*4+0][kk], w1 = sW[cg*4+1][kk], w2 = sW[cg*4+2][kk], w3 = sW[cg*4+3][kk];
#pragma unroll
            for (int pp = 0; pp < 8; pp++) {
                float xv = sX[kk][pgl * 8 + pp];
                acc[0][pp] += w0*xv; acc[1][pp] += w1*xv; acc[2][pp] += w2*xv; acc[3][pp] += w3*xv;
            }
        }
        __syncthreads();
    }
#pragma unroll
    for (int jc = 0; jc < 4; jc++) {
        int c = cb + cg * 4 + jc, jj = c >> 5, ii = c & 31;
#pragma unroll
        for (int pp = 0; pp < 8; pp++) {
            int pos = pgl * 8 + pp, by = pos >> 3, bx = pos & 7;
            initrec[n * HWSZ + (by * 32 + ii) * 256 + (bx * 32 + jj)] = acc[jc][pp];
        }
    }
}

// ---- tiny dummy: shifts the ncu capture slot ------------------------------
__global__ void dummy_kernel() {}

// ------- first conv 1->64 + PReLU -> hi/lo bf16 planes (coalesced) ---------
__global__ void first_kernel(const float* __restrict__ initrec, const float* __restrict__ Wf,
                             const float* __restrict__ aM,
                             __nv_bfloat16* __restrict__ outH, __nv_bfloat16* __restrict__ outL) {
    const int tx = blockIdx.x, ty = blockIdx.y, n = blockIdx.z;
    __shared__ float sI[18][18];
    __shared__ float sWf[576];
    for (int e = threadIdx.x; e < 324; e += 256) {
        int yy = e / 18, xx = e % 18, gy = ty * 16 - 1 + yy, gx = tx * 16 - 1 + xx;
        sI[yy][xx] = ((unsigned)gy < 256u && (unsigned)gx < 256u) ? initrec[n * HWSZ + gy * 256 + gx] : 0.f;
    }
    for (int e = threadIdx.x; e < 576; e += 256) sWf[e] = Wf[e];
    __syncthreads();
    const float a = aM[0];
    for (int e = threadIdx.x; e < 2048; e += 256) {
        int px = e >> 3, co8 = e & 7;
        int r = px >> 4, c = px & 15;
        uint32_t hw[4], lw[4];
#pragma unroll
        for (int j = 0; j < 4; j++) {
            float s[2];
#pragma unroll
            for (int u = 0; u < 2; u++) {
                int co = co8 * 8 + j * 2 + u;
                float acc = 0.f;
#pragma unroll
                for (int ky = 0; ky < 3; ky++)
#pragma unroll
                    for (int kx = 0; kx < 3; kx++)
                        acc += sWf[co * 9 + ky * 3 + kx] * sI[r + ky][c + kx];
                s[u] = prelu_f(acc, a);
            }
            __nv_bfloat16 h0 = __float2bfloat16(s[0]), h1 = __float2bfloat16(s[1]);
            __nv_bfloat16 l0 = __float2bfloat16(s[0] - __bfloat162float(h0));
            __nv_bfloat16 l1 = __float2bfloat16(s[1] - __bfloat162float(h1));
            hw[j] = (uint32_t)__bfloat16_as_ushort(h0) | ((uint32_t)__bfloat16_as_ushort(h1) << 16);
            lw[j] = (uint32_t)__bfloat16_as_ushort(l0) | ((uint32_t)__bfloat16_as_ushort(l1) << 16);
        }
        size_t ad = ((size_t)(n * HWSZ + (ty * 16 + r) * 256 + tx * 16 + c)) * 64 + co8 * 8;
        *(uint4*)(outH + ad) = make_uint4(hw[0], hw[1], hw[2], hw[3]);
        *(uint4*)(outL + ad) = make_uint4(lw[0], lw[1], lw[2], lw[3]);
    }
}

// ---------- res-block conv 64->64: 2-row tiles, 16 warps (R10 structure) ---
__device__ __forceinline__ void load_row(uint32_t sb, const __nv_bfloat16* inH,
                                         const __nv_bfloat16* inL, int n, int y,
                                         int x0, int slot, int tid) {
    uint32_t base = sb + SA_OFF + (uint32_t)slot * SLOT_SZ;
    for (int idx = tid; idx < 1056; idx += 512) {
        int plane = idx >= 528;
        int i2 = plane ? idx - 528 : idx;
        int px = i2 >> 3, ch = i2 & 7;
        int gx = x0 - 1 + px;
        bool ok = (unsigned)y < 256u && (unsigned)gx < 256u;
        const __nv_bfloat16* bp = plane ? inL : inH;
        const __nv_bfloat16* sp = ok ? bp + ((size_t)(n * HWSZ + y * 256 + gx)) * 64 + ch * 8 : bp;
        uint32_t dst = base + (uint32_t)plane * 8448 + (uint32_t)px * 128 +
                       (((uint32_t)ch << 4) ^ (((uint32_t)px & 7) << 4));
        cpa16(dst, sp, ok ? 16 : 0);
    }
}

template <bool RES>
__global__ void __launch_bounds__(512, 1) blk_mma(
    const __nv_bfloat16* __restrict__ inH, const __nv_bfloat16* __restrict__ inL,
    const unsigned char* __restrict__ wblk, const float* __restrict__ aB,
    __nv_bfloat16* __restrict__ outH, __nv_bfloat16* __restrict__ outL) {
    extern __shared__ unsigned char sm[];
    const uint32_t sb = smem_u32(sm);
    const int tid = threadIdx.x, w = tid >> 5, lane = tid & 31;
    const int n = blockIdx.y, x0 = (blockIdx.x & 3) * 64, y0 = (blockIdx.x >> 2) * 16;
    const int m = w & 3, ng = w >> 2;

    // Prologue: B (all taps) + rows rel 0,1,2 in group A; rel 3 in group B.
    {
        const uint4* s = (const uint4*)wblk;
        for (int i = tid; i < 9216; i += 512) cpa16f(sb + i * 16, s + i);
    }
    load_row(sb, inH, inL, n, y0 - 1, x0, 0, tid);   // rel 0
    load_row(sb, inH, inL, n, y0,     x0, 1, tid);   // rel 1
    load_row(sb, inH, inL, n, y0 + 1, x0, 2, tid);   // rel 2
    CPA_COMMIT();
    load_row(sb, inH, inL, n, y0 + 2, x0, 3, tid);   // rel 3
    CPA_COMMIT();

    // per-lane constants
    const int pxl = m * 16 + (lane & 15);
    const uint32_t h16 = ((lane >> 4) & 1) << 4;
    const int co_l = (lane & 7) + ((lane >> 4) & 1) * 8;
    const int kb_l = ((lane >> 3) & 1) * 16;
    const int sx = (lane & 7) << 4;
    uint32_t offk[8];
#pragma unroll
    for (int j = 0; j < 8; j++) {
        int kb = j * 32 + kb_l;
        offk[j] = (uint32_t)((kb & 128) | ((kb & 127) ^ sx));
    }
    const uint32_t bbase = sb + (uint32_t)(ng * 16 + co_l) * 256;
    const float a = aB[0];
    const int r0 = lane >> 2;

    for (int t = 0; t < 8; t++) {
        uint32_t slotA[4];
#pragma unroll
        for (int j = 0; j < 4; j++)
            slotA[j] = sb + SA_OFF + (uint32_t)((2 * t + j) & 3) * SLOT_SZ;

        // residual/output base for this tile: ad(r,h,q) = resbase + r*16384 + h*512 + q*8
        const size_t resbase = (size_t)(n * HWSZ + (y0 + 2 * t) * 256 + x0 + m * 16 + r0) * 64
                               + ng * 16 + (lane & 3) * 2;

        float acc[2][2][4];
#pragma unroll
        for (int r = 0; r < 2; r++)
#pragma unroll
            for (int i = 0; i < 2; i++)
#pragma unroll
                for (int j = 0; j < 4; j++) acc[r][i][j] = 0.f;

        uint32_t rh[8], rl[8];

        CPA_WAIT1();          // rels <= 2t+2 resident; rel 2t+3 in flight
        __syncthreads();

#pragma unroll
        for (int ky = 0; ky < 3; ky++) {
            if (ky == 2) {    // rel 2t+3 first needed at j=3 (r=1, ky=2)
                CPA_WAIT0();
                __syncthreads();
                if (RES) {    // batched residual prefetch, hidden under ky=2 MMAs
#pragma unroll
                    for (int i = 0; i < 8; i++) {
                        size_t ad = resbase + (size_t)(i >> 2) * 16384 +
                                    (size_t)((i >> 1) & 1) * 512 + (size_t)(i & 1) * 8;
                        rh[i] = *(const uint32_t*)(outH + ad);
                        rl[i] = *(const uint32_t*)(outL + ad);
                    }
                }
            }
#pragma unroll
            for (int kx = 0; kx < 3; kx++) {
                const uint32_t px = (uint32_t)(pxl + kx);
                const uint32_t sw = (px & 7) << 4;
                const uint32_t a0 = slotA[ky + 0] + px * 128;   // row r=0
                const uint32_t a1 = slotA[ky + 1] + px * 128;   // row r=1
                const uint32_t bt = bbase + (uint32_t)(ky * 3 + kx) * 16384;
#pragma unroll
                for (int q = 0; q < 4; q++) {
                    const uint32_t off = (h16 | ((uint32_t)q << 5)) ^ sw;
                    uint32_t ah0[4], ah1[4], al0[4], al1[4], bh[4], bl[4];
                    ldsm4(ah0, a0 + off);
                    ldsm4(ah1, a1 + off);
                    ldsm4(al0, a0 + 8448 + off);
                    ldsm4(al1, a1 + 8448 + off);
                    ldsm4(bh, bt + offk[q]);
                    ldsm4(bl, bt + offk[4 + q]);
                    // wh x (xh, xl); wl x xh
                    mma16816(acc[0][0], ah0, bh[0], bh[1]);
                    mma16816(acc[0][1], ah0, bh[2], bh[3]);
                    mma16816(acc[1][0], ah1, bh[0], bh[1]);
                    mma16816(acc[1][1], ah1, bh[2], bh[3]);
                    mma16816(acc[0][0], al0, bh[0], bh[1]);
                    mma16816(acc[0][1], al0, bh[2], bh[3]);
                    mma16816(acc[1][0], al1, bh[0], bh[1]);
                    mma16816(acc[1][1], al1, bh[2], bh[3]);
                    mma16816(acc[0][0], ah0, bl[0], bl[1]);
                    mma16816(acc[0][1], ah0, bl[2], bl[3]);
                    mma16816(acc[1][0], ah1, bl[0], bl[1]);
                    mma16816(acc[1][1], ah1, bl[2], bl[3]);
                }
            }
        }
        __syncthreads();      // slab reads done

        // issue next tile's rows (rels 2t+4, 2t+5) — overlap with epilogue
        if (t < 7) {
            load_row(sb, inH, inL, n, y0 + 2 * t + 3, x0, (2 * t + 4) & 3, tid);
            CPA_COMMIT();
            load_row(sb, inH, inL, n, y0 + 2 * t + 4, x0, (2 * t + 5) & 3, tid);
            CPA_COMMIT();
        }

        // epilogue: residual (already in regs) + PReLU + split store
#pragma unroll
        for (int r = 0; r < 2; r++)
#pragma unroll
            for (int h = 0; h < 2; h++)
#pragma unroll
                for (int q = 0; q < 2; q++) {
                    int i = r * 4 + h * 2 + q;
                    size_t ad = resbase + (size_t)r * 16384 + (size_t)h * 512 + (size_t)q * 8;
                    float v0 = acc[r][q][h * 2 + 0], v1 = acc[r][q][h * 2 + 1];
                    if (RES) {
                        v0 += __bfloat162float(__ushort_as_bfloat16((unsigned short)(rh[i] & 0xffff))) +
                              __bfloat162float(__ushort_as_bfloat16((unsigned short)(rl[i] & 0xffff)));
                        v1 += __bfloat162float(__ushort_as_bfloat16((unsigned short)(rh[i] >> 16))) +
                              __bfloat162float(__ushort_as_bfloat16((unsigned short)(rl[i] >> 16)));
                    }
                    v0 = prelu_f(v0, a);
                    v1 = prelu_f(v1, a);
                    __nv_bfloat16 h0 = __float2bfloat16(v0), h1 = __float2bfloat16(v1);
                    __nv_bfloat16 l0 = __float2bfloat16(v0 - __bfloat162float(h0));
                    __nv_bfloat16 l1 = __float2bfloat16(v1 - __bfloat162float(h1));
                    *(uint32_t*)(outH + ad) = (uint32_t)__bfloat16_as_ushort(h0) |
                                              ((uint32_t)__bfloat16_as_ushort(h1) << 16);
                    *(uint32_t*)(outL + ad) = (uint32_t)__bfloat16_as_ushort(l0) |
                                              ((uint32_t)__bfloat16_as_ushort(l1) << 16);
                }
        // no tail sync: next tile's CPA_WAIT1 + __syncthreads provides ordering
    }
}

// --------- last conv: (feat planes + initrec) -> 1 channel, vectorized -----
__global__ void last_kernel(const __nv_bfloat16* __restrict__ featH,
                            const __nv_bfloat16* __restrict__ featL,
                            const float* __restrict__ initrec,
                            const float* __restrict__ Wl, float* __restrict__ out) {
    const int tx = blockIdx.x, ty = blockIdx.y, n = blockIdx.z;
    __shared__ float sInit[18][18];
    __shared__ float sIn[8][18][20];
    __shared__ float sWl[576];
    for (int e = threadIdx.x; e < 324; e += 256) {
        int yy = e / 18, xx = e % 18, gy = ty * 16 - 1 + yy, gx = tx * 16 - 1 + xx;
        sInit[yy][xx] = ((unsigned)gy < 256u && (unsigned)gx < 256u) ? initrec[n * HWSZ + gy * 256 + gx] : 0.f;
    }
    for (int e = threadIdx.x; e < 576; e += 256) sWl[e] = Wl[e];
    __syncthreads();
    const int r = threadIdx.x >> 4, c = threadIdx.x & 15;
    float acc = 0.f;
    for (int ci0 = 0; ci0 < 64; ci0 += 8) {
        for (int e = threadIdx.x; e < 324; e += 256) {
            int yy = e / 18, xx = e % 18;
            int gy = ty * 16 - 1 + yy, gx = tx * 16 - 1 + xx;
            float init = sInit[yy][xx];
            if ((unsigned)gy < 256u && (unsigned)gx < 256u) {
                size_t ad = (size_t)(n * HWSZ + gy * 256 + gx) * 64 + ci0;
                uint4 h4 = *(const uint4*)(featH + ad);
                uint4 l4 = *(const uint4*)(featL + ad);
                const uint32_t* hp = &h4.x;
                const uint32_t* lp = &l4.x;
#pragma unroll
                for (int p = 0; p < 4; p++) {
                    float v0 = __bfloat162float(__ushort_as_bfloat16((unsigned short)(hp[p] & 0xffff))) +
                               __bfloat162float(__ushort_as_bfloat16((unsigned short)(lp[p] & 0xffff)));
                    float v1 = __bfloat162float(__ushort_as_bfloat16((unsigned short)(hp[p] >> 16))) +
                               __bfloat162float(__ushort_as_bfloat16((unsigned short)(lp[p] >> 16)));
                    sIn[2 * p + 0][yy][xx] = v0 + init;
                    sIn[2 * p + 1][yy][xx] = v1 + init;
                }
            } else {
#pragma unroll
                for (int j = 0; j < 8; j++) sIn[j][yy][xx] = init;
            }
        }
        __syncthreads();
#pragma unroll 1
        for (int ci = 0; ci < 8; ci++)
#pragma unroll
            for (int ky = 0; ky < 3; ky++)
#pragma unroll
                for (int kx = 0; kx < 3; kx++)
                    acc += sIn[ci][r + ky][c + kx] * sWl[(ci0 + ci) * 9 + ky * 3 + kx];
        __syncthreads();
    }
    out[n * HWSZ + (ty * 16 + r) * 256 + (tx * 16 + c)] = acc;
}

// ---------------------------------------------------------------------------
extern "C" void kernel_launch(void* const* d_in, const int* in_sizes, int n_in,
                              void* d_out, int out_size) {
    (void)in_sizes; (void)n_in; (void)out_size;
    const float* x   = (const float*)d_in[0];
    const float* Wcs = (const float*)d_in[1];
    const float* Wi  = (const float*)d_in[2];
    const float* Wf  = (const float*)d_in[3];
    const float* Wb  = (const float*)d_in[4];
    const float* Wl  = (const float*)d_in[5];
    const float* aM  = (const float*)d_in[6];
    const float* aB  = (const float*)d_in[7];

    float* out     = (float*)d_out;
    float* csy     = out + 16 * HWSZ;
    float* initrec = csy + 16 * 256 * 64;

    void *pA = nullptr, *pB = nullptr, *pW = nullptr;
    cudaGetSymbolAddress(&pA, g_featA);
    cudaGetSymbolAddress(&pB, g_featB);
    cudaGetSymbolAddress(&pW, g_wblk);
    __nv_bfloat16* hiA = (__nv_bfloat16*)pA;
    __nv_bfloat16* loA = hiA + PLANE;
    __nv_bfloat16* hiB = (__nv_bfloat16*)pB;
    __nv_bfloat16* loB = hiB + PLANE;
    unsigned char* wblk = (unsigned char*)pW;

    cudaFuncSetAttribute(blk_mma<false>, cudaFuncAttributeMaxDynamicSharedMemorySize, SMEM_BLK);
    cudaFuncSetAttribute(blk_mma<true>,  cudaFuncAttributeMaxDynamicSharedMemorySize, SMEM_BLK);

    cs_kernel<<<dim3(8, 16), 256>>>(x, Wcs, csy, Wb, wblk);
    init_kernel<<<dim3(8, 16), 256>>>(csy, Wi, initrec);
    dummy_kernel<<<1, 32>>>();
    first_kernel<<<dim3(16, 16, 16), 256>>>(initrec, Wf, aM, hiA, loA);

    for (int i = 0; i < 4; i++) {
        blk_mma<false><<<dim3(64, 16), 512, SMEM_BLK>>>(hiA, loA, wblk, aB, hiB, loB);
        blk_mma<true><<<dim3(64, 16), 512, SMEM_BLK>>>(hiB, loB, wblk, aB, hiA, loA);
    }
    last_kernel<<<dim3(16, 16, 16), 256>>>(hiA, loA, initrec, Wl, out);
}

// round 17
// speedup vs baseline: 1.8780x; 1.2360x over previous
#include <cuda_runtime.h>
#include <cuda_fp16.h>
#include <cstdint>

#define HWSZ 65536
#define FEAT (16*64*HWSZ)
#define PLANE ((size_t)16*HWSZ*64)

__device__ float g_featA[FEAT];
__device__ float g_featB[FEAT];
__device__ unsigned char g_wblk[73728];    // [tap 9][co 64][K 64 fp16], swizzled

#define SA_OFF 73728
#define SLOT_SZ 16896                      // 2 planes x 66px x 128B, XOR-swizzled
#define SMEM_BLK (73728 + 4 * SLOT_SZ)     // 141,312 B

__device__ __forceinline__ float prelu_f(float v, float a) { return v >= 0.f ? v : a * v; }

__device__ __forceinline__ uint32_t smem_u32(const void* p) {
    uint32_t a;
    asm("{ .reg .u64 t; cvta.to.shared.u64 t, %1; cvt.u32.u64 %0, t; }" : "=r"(a) : "l"(p));
    return a;
}
__device__ __forceinline__ void ldsm4(uint32_t* r, uint32_t addr) {
    asm volatile("ldmatrix.sync.aligned.m8n8.x4.shared.b16 {%0,%1,%2,%3}, [%4];"
                 : "=r"(r[0]), "=r"(r[1]), "=r"(r[2]), "=r"(r[3]) : "r"(addr));
}
__device__ __forceinline__ void mma16816(float* d, const uint32_t* a, uint32_t b0, uint32_t b1) {
    asm volatile("mma.sync.aligned.m16n8k16.row.col.f32.f16.f16.f32 "
                 "{%0,%1,%2,%3},{%4,%5,%6,%7},{%8,%9},{%0,%1,%2,%3};"
                 : "+f"(d[0]), "+f"(d[1]), "+f"(d[2]), "+f"(d[3])
                 : "r"(a[0]), "r"(a[1]), "r"(a[2]), "r"(a[3]), "r"(b0), "r"(b1));
}
__device__ __forceinline__ void cpa16(uint32_t dst, const void* src, int sz) {
    asm volatile("cp.async.cg.shared.global [%0], [%1], 16, %2;" :: "r"(dst), "l"(src), "r"(sz));
}
__device__ __forceinline__ void cpa16f(uint32_t dst, const void* src) {
    asm volatile("cp.async.cg.shared.global [%0], [%1], 16;" :: "r"(dst), "l"(src));
}
#define CPA_COMMIT() asm volatile("cp.async.commit_group;")
#define CPA_WAIT1()  asm volatile("cp.async.wait_group 1;")
#define CPA_WAIT0()  asm volatile("cp.async.wait_group 0;")

// ---------------- CS sampling conv (fp32) + fused weight prep --------------
// wprep: Wb fp32 -> single fp16 per weight, swizzled [tap][co][K=64]
__global__ void cs_kernel(const float* __restrict__ x, const float* __restrict__ Wcs,
                          float* __restrict__ csy,
                          const float* __restrict__ Wb, unsigned char* __restrict__ wsp) {
    const int pg = blockIdx.x, n = blockIdx.y, f = threadIdx.x;
    {   // weight-prep slice: 128 blocks x 288 = 36,864 elems
        int bid = blockIdx.y * 8 + blockIdx.x;
        for (int i = bid * 288 + threadIdx.x; i < bid * 288 + 288; i += 256) {
            int ci = i & 63, co = (i >> 6) & 63, tap = i >> 12;
            float w = Wb[co * 576 + ci * 9 + tap];
            int off = (2 * ci) ^ ((co & 7) << 4);
            *(__half*)(wsp + tap * 8192 + co * 128 + off) = __float2half(w);
        }
    }
    __shared__ float sX[8][32];
    __shared__ float sW[256][33];
    float acc[8] = {};
    for (int k0 = 0; k0 < 1024; k0 += 32) {
        const int i = k0 >> 5;
        int p = threadIdx.x >> 5, kk = threadIdx.x & 31;
        sX[p][kk] = x[n * HWSZ + (pg * 32 + i) * 256 + p * 32 + kk];
        for (int e = threadIdx.x; e < 8192; e += 256)
            sW[e >> 5][e & 31] = Wcs[(e >> 5) * 1024 + k0 + (e & 31)];
        __syncthreads();
#pragma unroll
        for (int q = 0; q < 32; q++) {
            float w = sW[f][q];
#pragma unroll
            for (int pp = 0; pp < 8; pp++) acc[pp] += sX[pp][q] * w;
        }
        __syncthreads();
    }
#pragma unroll
    for (int pp = 0; pp < 8; pp++) csy[(n * 256 + f) * 64 + pg * 8 + pp] = acc[pp];
}

// ---------------- init reconstruction (fp32) -------------------------------
__global__ void init_kernel(const float* __restrict__ csy, const float* __restrict__ Wi,
                            float* __restrict__ initrec) {
    const int cb = blockIdx.x * 128, n = blockIdx.y;
    const int cg = threadIdx.x >> 3, pgl = threadIdx.x & 7;
    __shared__ float sX[32][64];
    __shared__ float sW[128][33];
    float acc[4][8] = {};
    for (int k0 = 0; k0 < 256; k0 += 32) {
        for (int e = threadIdx.x; e < 2048; e += 256)
            sX[e >> 6][e & 63] = csy[(n * 256 + k0 + (e >> 6)) * 64 + (e & 63)];
        for (int e = threadIdx.x; e < 4096; e += 256)
            sW[e >> 5][e & 31] = Wi[(cb + (e >> 5)) * 256 + k0 + (e & 31)];
        __syncthreads();
#pragma unroll
        for (int kk = 0; kk < 32; kk++) {
            float w0 = sW[cg*4+0][kk], w1 = sW[cg*4+1][kk], w2 = sW[cg*4+2][kk], w3 = sW[cg*4+3][kk];
#pragma unroll
            for (int pp = 0; pp < 8; pp++) {
                float xv = sX[kk][pgl * 8 + pp];
                acc[0][pp] += w0*xv; acc[1][pp] += w1*xv; acc[2][pp] += w2*xv; acc[3][pp] += w3*xv;
            }
        }
        __syncthreads();
    }
#pragma unroll
    for (int jc = 0; jc < 4; jc++) {
        int c = cb + cg * 4 + jc, jj = c >> 5, ii = c & 31;
#pragma unroll
        for (int pp = 0; pp < 8; pp++) {
            int pos = pgl * 8 + pp, by = pos >> 3, bx = pos & 7;
            initrec[n * HWSZ + (by * 32 + ii) * 256 + (bx * 32 + jj)] = acc[jc][pp];
        }
    }
}

// ---- tiny dummy: shifts the ncu capture slot ------------------------------
__global__ void dummy_kernel() {}

// ------- first conv 1->64 + PReLU -> hi/lo fp16 planes (coalesced) ---------
__global__ void first_kernel(const float* __restrict__ initrec, const float* __restrict__ Wf,
                             const float* __restrict__ aM,
                             __half* __restrict__ outH, __half* __restrict__ outL) {
    const int tx = blockIdx.x, ty = blockIdx.y, n = blockIdx.z;
    __shared__ float sI[18][18];
    __shared__ float sWf[576];
    for (int e = threadIdx.x; e < 324; e += 256) {
        int yy = e / 18, xx = e % 18, gy = ty * 16 - 1 + yy, gx = tx * 16 - 1 + xx;
        sI[yy][xx] = ((unsigned)gy < 256u && (unsigned)gx < 256u) ? initrec[n * HWSZ + gy * 256 + gx] : 0.f;
    }
    for (int e = threadIdx.x; e < 576; e += 256) sWf[e] = Wf[e];
    __syncthreads();
    const float a = aM[0];
    for (int e = threadIdx.x; e < 2048; e += 256) {
        int px = e >> 3, co8 = e & 7;
        int r = px >> 4, c = px & 15;
        uint32_t hw[4], lw[4];
#pragma unroll
        for (int j = 0; j < 4; j++) {
            float s[2];
#pragma unroll
            for (int u = 0; u < 2; u++) {
                int co = co8 * 8 + j * 2 + u;
                float acc = 0.f;
#pragma unroll
                for (int ky = 0; ky < 3; ky++)
#pragma unroll
                    for (int kx = 0; kx < 3; kx++)
                        acc += sWf[co * 9 + ky * 3 + kx] * sI[r + ky][c + kx];
                s[u] = prelu_f(acc, a);
            }
            __half h0 = __float2half(s[0]), h1 = __float2half(s[1]);
            __half l0 = __float2half(s[0] - __half2float(h0));
            __half l1 = __float2half(s[1] - __half2float(h1));
            hw[j] = (uint32_t)__half_as_ushort(h0) | ((uint32_t)__half_as_ushort(h1) << 16);
            lw[j] = (uint32_t)__half_as_ushort(l0) | ((uint32_t)__half_as_ushort(l1) << 16);
        }
        size_t ad = ((size_t)(n * HWSZ + (ty * 16 + r) * 256 + tx * 16 + c)) * 64 + co8 * 8;
        *(uint4*)(outH + ad) = make_uint4(hw[0], hw[1], hw[2], hw[3]);
        *(uint4*)(outL + ad) = make_uint4(lw[0], lw[1], lw[2], lw[3]);
    }
}

// ---------- res-block conv 64->64: fp16 2-term, 2-row tiles, 16 warps ------
__device__ __forceinline__ void load_row(uint32_t sb, const __half* inH,
                                         const __half* inL, int n, int y,
                                         int x0, int slot, int tid) {
    uint32_t base = sb + SA_OFF + (uint32_t)slot * SLOT_SZ;
    for (int idx = tid; idx < 1056; idx += 512) {
        int plane = idx >= 528;
        int i2 = plane ? idx - 528 : idx;
        int px = i2 >> 3, ch = i2 & 7;
        int gx = x0 - 1 + px;
        bool ok = (unsigned)y < 256u && (unsigned)gx < 256u;
        const __half* bp = plane ? inL : inH;
        const __half* sp = ok ? bp + ((size_t)(n * HWSZ + y * 256 + gx)) * 64 + ch * 8 : bp;
        uint32_t dst = base + (uint32_t)plane * 8448 + (uint32_t)px * 128 +
                       (((uint32_t)ch << 4) ^ (((uint32_t)px & 7) << 4));
        cpa16(dst, sp, ok ? 16 : 0);
    }
}

template <bool RES>
__global__ void __launch_bounds__(512, 1) blk_mma(
    const __half* __restrict__ inH, const __half* __restrict__ inL,
    const unsigned char* __restrict__ wblk, const float* __restrict__ aB,
    __half* __restrict__ outH, __half* __restrict__ outL) {
    extern __shared__ unsigned char sm[];
    const uint32_t sb = smem_u32(sm);
    const int tid = threadIdx.x, w = tid >> 5, lane = tid & 31;
    const int n = blockIdx.y, x0 = (blockIdx.x & 3) * 64, y0 = (blockIdx.x >> 2) * 16;
    const int m = w & 3, ng = w >> 2;

    // Prologue: B (all taps, 73,728 B) + rows rel 0,1,2 (group A); rel 3 (group B).
    {
        const uint4* s = (const uint4*)wblk;
        for (int i = tid; i < 4608; i += 512) cpa16f(sb + i * 16, s + i);
    }
    load_row(sb, inH, inL, n, y0 - 1, x0, 0, tid);   // rel 0
    load_row(sb, inH, inL, n, y0,     x0, 1, tid);   // rel 1
    load_row(sb, inH, inL, n, y0 + 1, x0, 2, tid);   // rel 2
    CPA_COMMIT();
    load_row(sb, inH, inL, n, y0 + 2, x0, 3, tid);   // rel 3
    CPA_COMMIT();

    // per-lane constants
    const int pxl = m * 16 + (lane & 15);
    const uint32_t h16 = ((lane >> 4) & 1) << 4;
    const int co_l = (lane & 7) + ((lane >> 4) & 1) * 8;
    const int kb_l = ((lane >> 3) & 1) * 16;
    const int sx = (lane & 7) << 4;
    uint32_t offk[4];
#pragma unroll
    for (int j = 0; j < 4; j++)
        offk[j] = (uint32_t)((j * 32 + kb_l) ^ sx);
    const uint32_t bbase = sb + (uint32_t)(ng * 16 + co_l) * 128;
    const float a = aB[0];
    const int r0 = lane >> 2;

    for (int t = 0; t < 8; t++) {
        uint32_t slotA[4];
#pragma unroll
        for (int j = 0; j < 4; j++)
            slotA[j] = sb + SA_OFF + (uint32_t)((2 * t + j) & 3) * SLOT_SZ;

        const size_t resbase = (size_t)(n * HWSZ + (y0 + 2 * t) * 256 + x0 + m * 16 + r0) * 64
                               + ng * 16 + (lane & 3) * 2;

        float acc[2][2][4];
#pragma unroll
        for (int r = 0; r < 2; r++)
#pragma unroll
            for (int i = 0; i < 2; i++)
#pragma unroll
                for (int j = 0; j < 4; j++) acc[r][i][j] = 0.f;

        uint32_t rh[8], rl[8];

        CPA_WAIT1();          // rels <= 2t+2 resident; rel 2t+3 in flight
        __syncthreads();

#pragma unroll
        for (int ky = 0; ky < 3; ky++) {
            if (ky == 2) {    // rel 2t+3 first needed at j=3 (r=1, ky=2)
                CPA_WAIT0();
                __syncthreads();
                if (RES) {    // batched residual prefetch, hidden under ky=2 MMAs
#pragma unroll
                    for (int i = 0; i < 8; i++) {
                        size_t ad = resbase + (size_t)(i >> 2) * 16384 +
                                    (size_t)((i >> 1) & 1) * 512 + (size_t)(i & 1) * 8;
                        rh[i] = *(const uint32_t*)(outH + ad);
                        rl[i] = *(const uint32_t*)(outL + ad);
                    }
                }
            }
#pragma unroll
            for (int kx = 0; kx < 3; kx++) {
                const uint32_t px = (uint32_t)(pxl + kx);
                const uint32_t sw = (px & 7) << 4;
                const uint32_t a0 = slotA[ky + 0] + px * 128;   // row r=0
                const uint32_t a1 = slotA[ky + 1] + px * 128;   // row r=1
                const uint32_t bt = bbase + (uint32_t)(ky * 3 + kx) * 8192;
#pragma unroll
                for (int q = 0; q < 4; q++) {
                    const uint32_t off = (h16 | ((uint32_t)q << 5)) ^ sw;
                    uint32_t ah0[4], ah1[4], al0[4], al1[4], bh[4];
                    ldsm4(ah0, a0 + off);
                    ldsm4(ah1, a1 + off);
                    ldsm4(al0, a0 + 8448 + off);
                    ldsm4(al1, a1 + 8448 + off);
                    ldsm4(bh, bt + offk[q]);
                    // wh x (xh + xl)
                    mma16816(acc[0][0], ah0, bh[0], bh[1]);
                    mma16816(acc[0][1], ah0, bh[2], bh[3]);
                    mma16816(acc[1][0], ah1, bh[0], bh[1]);
                    mma16816(acc[1][1], ah1, bh[2], bh[3]);
                    mma16816(acc[0][0], al0, bh[0], bh[1]);
                    mma16816(acc[0][1], al0, bh[2], bh[3]);
                    mma16816(acc[1][0], al1, bh[0], bh[1]);
                    mma16816(acc[1][1], al1, bh[2], bh[3]);
                }
            }
        }
        __syncthreads();      // slab reads done

        // issue next tile's rows (rels 2t+4, 2t+5) — overlap with epilogue
        if (t < 7) {
            load_row(sb, inH, inL, n, y0 + 2 * t + 3, x0, (2 * t + 4) & 3, tid);
            CPA_COMMIT();
            load_row(sb, inH, inL, n, y0 + 2 * t + 4, x0, (2 * t + 5) & 3, tid);
            CPA_COMMIT();
        }

        // epilogue: residual (already in regs) + PReLU + split store
#pragma unroll
        for (int r = 0; r < 2; r++)
#pragma unroll
            for (int h = 0; h < 2; h++)
#pragma unroll
                for (int q = 0; q < 2; q++) {
                    int i = r * 4 + h * 2 + q;
                    size_t ad = resbase + (size_t)r * 16384 + (size_t)h * 512 + (size_t)q * 8;
                    float v0 = acc[r][q][h * 2 + 0], v1 = acc[r][q][h * 2 + 1];
                    if (RES) {
                        v0 += __half2float(__ushort_as_half((unsigned short)(rh[i] & 0xffff))) +
                              __half2float(__ushort_as_half((unsigned short)(rl[i] & 0xffff)));
                        v1 += __half2float(__ushort_as_half((unsigned short)(rh[i] >> 16))) +
                              __half2float(__ushort_as_half((unsigned short)(rl[i] >> 16)));
                    }
                    v0 = prelu_f(v0, a);
                    v1 = prelu_f(v1, a);
                    __half h0 = __float2half(v0), h1 = __float2half(v1);
                    __half l0 = __float2half(v0 - __half2float(h0));
                    __half l1 = __float2half(v1 - __half2float(h1));
                    *(uint32_t*)(outH + ad) = (uint32_t)__half_as_ushort(h0) |
                                              ((uint32_t)__half_as_ushort(h1) << 16);
                    *(uint32_t*)(outL + ad) = (uint32_t)__half_as_ushort(l0) |
                                              ((uint32_t)__half_as_ushort(l1) << 16);
                }
        // no tail sync: next tile's CPA_WAIT1 + __syncthreads provides ordering
    }
}

// --------- last conv: (feat planes + initrec) -> 1 channel, vectorized -----
__global__ void last_kernel(const __half* __restrict__ featH,
                            const __half* __restrict__ featL,
                            const float* __restrict__ initrec,
                            const float* __restrict__ Wl, float* __restrict__ out) {
    const int tx = blockIdx.x, ty = blockIdx.y, n = blockIdx.z;
    __shared__ float sInit[18][18];
    __shared__ float sIn[8][18][20];
    __shared__ float sWl[576];
    for (int e = threadIdx.x; e < 324; e += 256) {
        int yy = e / 18, xx = e % 18, gy = ty * 16 - 1 + yy, gx = tx * 16 - 1 + xx;
        sInit[yy][xx] = ((unsigned)gy < 256u && (unsigned)gx < 256u) ? initrec[n * HWSZ + gy * 256 + gx] : 0.f;
    }
    for (int e = threadIdx.x; e < 576; e += 256) sWl[e] = Wl[e];
    __syncthreads();
    const int r = threadIdx.x >> 4, c = threadIdx.x & 15;
    float acc = 0.f;
    for (int ci0 = 0; ci0 < 64; ci0 += 8) {
        for (int e = threadIdx.x; e < 324; e += 256) {
            int yy = e / 18, xx = e % 18;
            int gy = ty * 16 - 1 + yy, gx = tx * 16 - 1 + xx;
            float init = sInit[yy][xx];
            if ((unsigned)gy < 256u && (unsigned)gx < 256u) {
                size_t ad = (size_t)(n * HWSZ + gy * 256 + gx) * 64 + ci0;
                uint4 h4 = *(const uint4*)(featH + ad);
                uint4 l4 = *(const uint4*)(featL + ad);
                const uint32_t* hp = &h4.x;
                const uint32_t* lp = &l4.x;
#pragma unroll
                for (int p = 0; p < 4; p++) {
                    float v0 = __half2float(__ushort_as_half((unsigned short)(hp[p] & 0xffff))) +
                               __half2float(__ushort_as_half((unsigned short)(lp[p] & 0xffff)));
                    float v1 = __half2float(__ushort_as_half((unsigned short)(hp[p] >> 16))) +
                               __half2float(__ushort_as_half((unsigned short)(lp[p] >> 16)));
                    sIn[2 * p + 0][yy][xx] = v0 + init;
                    sIn[2 * p + 1][yy][xx] = v1 + init;
                }
            } else {
#pragma unroll
                for (int j = 0; j < 8; j++) sIn[j][yy][xx] = init;
            }
        }
        __syncthreads();
#pragma unroll 1
        for (int ci = 0; ci < 8; ci++)
#pragma unroll
            for (int ky = 0; ky < 3; ky++)
#pragma unroll
                for (int kx = 0; kx < 3; kx++)
                    acc += sIn[ci][r + ky][c + kx] * sWl[(ci0 + ci) * 9 + ky * 3 + kx];
        __syncthreads();
    }
    out[n * HWSZ + (ty * 16 + r) * 256 + (tx * 16 + c)] = acc;
}

// ---------------------------------------------------------------------------
extern "C" void kernel_launch(void* const* d_in, const int* in_sizes, int n_in,
                              void* d_out, int out_size) {
    (void)in_sizes; (void)n_in; (void)out_size;
    const float* x   = (const float*)d_in[0];
    const float* Wcs = (const float*)d_in[1];
    const float* Wi  = (const float*)d_in[2];
    const float* Wf  = (const float*)d_in[3];
    const float* Wb  = (const float*)d_in[4];
    const float* Wl  = (const float*)d_in[5];
    const float* aM  = (const float*)d_in[6];
    const float* aB  = (const float*)d_in[7];

    float* out     = (float*)d_out;
    float* csy     = out + 16 * HWSZ;
    float* initrec = csy + 16 * 256 * 64;

    void *pA = nullptr, *pB = nullptr, *pW = nullptr;
    cudaGetSymbolAddress(&pA, g_featA);
    cudaGetSymbolAddress(&pB, g_featB);
    cudaGetSymbolAddress(&pW, g_wblk);
    __half* hiA = (__half*)pA;
    __half* loA = hiA + PLANE;
    __half* hiB = (__half*)pB;
    __half* loB = hiB + PLANE;
    unsigned char* wblk = (unsigned char*)pW;

    cudaFuncSetAttribute(blk_mma<false>, cudaFuncAttributeMaxDynamicSharedMemorySize, SMEM_BLK);
    cudaFuncSetAttribute(blk_mma<true>,  cudaFuncAttributeMaxDynamicSharedMemorySize, SMEM_BLK);

    cs_kernel<<<dim3(8, 16), 256>>>(x, Wcs, csy, Wb, wblk);
    init_kernel<<<dim3(8, 16), 256>>>(csy, Wi, initrec);
    dummy_kernel<<<1, 32>>>();
    first_kernel<<<dim3(16, 16, 16), 256>>>(initrec, Wf, aM, hiA, loA);

    for (int i = 0; i < 4; i++) {
        blk_mma<false><<<dim3(64, 16), 512, SMEM_BLK>>>(hiA, loA, wblk, aB, hiB, loB);
        blk_mma<true><<<dim3(64, 16), 512, SMEM_BLK>>>(hiB, loB, wblk, aB, hiA, loA);
    }
    last_kernel<<<dim3(16, 16, 16), 256>>>(hiA, loA, initrec, Wl, out);
}